// round 4
// baseline (speedup 1.0000x reference)
#include <cuda_runtime.h>
#include <cuda_bf16.h>
#include <math.h>

// Problem dims (fixed by the dataset)
#define BB   2
#define SS   2048
#define DD   1024
#define HH   16
#define KVH  8
#define DK   64
#define FD   2752
#define NL   4
#define VV   32000
#define MM   (BB*SS)          // 4096 token rows

// ---------------- scratch (device globals: no allocations allowed) ----------
__device__ float g_x [MM*DD];
__device__ float g_h [MM*DD];
__device__ float g_q [MM*DD];
__device__ float g_k [MM*(KVH*DK)];
__device__ float g_v [MM*(KVH*DK)];
__device__ float g_o [MM*DD];
__device__ float g_f1[(size_t)MM*FD];
__device__ float g_f2[(size_t)MM*FD];

// ---------------- embedding gather ----------------
__global__ void embed_kernel(const int* __restrict__ tokens,
                             const float* __restrict__ emb,
                             float* __restrict__ x) {
    int row = blockIdx.x;
    int tok = tokens[row];
    const float4* src = (const float4*)(emb + (size_t)tok * DD);
    float4*       dst = (float4*)(x + (size_t)row * DD);
    dst[threadIdx.x] = src[threadIdx.x];
}

// ---------------- rmsnorm ----------------
__global__ void rmsnorm_kernel(const float* __restrict__ x,
                               const float* __restrict__ g,
                               float* __restrict__ out) {
    int row = blockIdx.x;
    const float4* xr = (const float4*)(x + (size_t)row * DD);
    float4 v = xr[threadIdx.x];
    float ss = v.x*v.x + v.y*v.y + v.z*v.z + v.w*v.w;
    #pragma unroll
    for (int o = 16; o; o >>= 1) ss += __shfl_xor_sync(0xffffffffu, ss, o);
    __shared__ float red[8];
    if ((threadIdx.x & 31) == 0) red[threadIdx.x >> 5] = ss;
    __syncthreads();
    if (threadIdx.x < 8) {
        float r = red[threadIdx.x];
        #pragma unroll
        for (int o = 4; o; o >>= 1) r += __shfl_xor_sync(0xffu, r, o);
        if (threadIdx.x == 0) red[0] = r;
    }
    __syncthreads();
    float inv = rsqrtf(red[0] * (1.0f / DD) + 1e-6f);
    const float4* g4 = (const float4*)g;
    float4 gg = g4[threadIdx.x];
    float4 ov = make_float4(v.x*inv*gg.x, v.y*inv*gg.y, v.z*inv*gg.z, v.w*inv*gg.w);
    ((float4*)(out + (size_t)row * DD))[threadIdx.x] = ov;
}

// ---------------- rope (interleaved pairs) ----------------
__global__ void rope_kernel(float* __restrict__ buf,
                            const float* __restrict__ cosb,
                            const float* __restrict__ sinb,
                            int nheads, int total) {
    int idx = blockIdx.x * blockDim.x + threadIdx.x;
    if (idx >= total) return;
    int p    = idx & 31;
    int hrow = idx >> 5;
    int row  = hrow / nheads;
    int s    = row & (SS - 1);
    float c  = cosb[s * 32 + p];
    float sn = sinb[s * 32 + p];
    float* base = buf + (size_t)hrow * DK + p * 2;
    float xr = base[0], xi = base[1];
    base[0] = xr * c - xi * sn;
    base[1] = xr * sn + xi * c;
}

// ---------------- flash attention (online softmax, causal, GQA n_rep=2) ----
#define ABM 16
#define ABN 32
__global__ __launch_bounds__(512)
void attn_kernel(const float* __restrict__ Q, const float* __restrict__ K,
                 const float* __restrict__ V, float* __restrict__ O) {
    int q0   = blockIdx.x * ABM;
    int h    = blockIdx.y;
    int b    = blockIdx.z;
    int kh   = h >> 1;
    int lane = threadIdx.x;
    int wy   = threadIdx.y;
    int t    = wy * 32 + lane;

    __shared__ float q_sh[ABM][DK];
    __shared__ float k_sh[ABN][DK + 1];
    __shared__ float v_sh[ABN][DK + 1];

    for (int idx = t; idx < ABM * DK; idx += 512) {
        int r = idx >> 6, c = idx & 63;
        q_sh[r][c] = Q[((size_t)(b * SS + q0 + r) * HH + h) * DK + c] * 0.125f;
    }
    __syncthreads();

    int   iglob = q0 + wy;
    float m = -1e30f, l = 0.f, acc0 = 0.f, acc1 = 0.f;
    int ntiles = (q0 + ABM - 1) / ABN + 1;

    for (int kt = 0; kt < ntiles; kt++) {
        int kbase = kt * ABN;
        for (int idx = t; idx < ABN * DK; idx += 512) {
            int r = idx >> 6, c = idx & 63;
            size_t off = ((size_t)(b * SS + kbase + r) * KVH + kh) * DK + c;
            k_sh[r][c] = K[off];
            v_sh[r][c] = V[off];
        }
        __syncthreads();

        float s = 0.f;
        #pragma unroll 16
        for (int d = 0; d < DK; d++) s += q_sh[wy][d] * k_sh[lane][d];
        if (kbase + lane > iglob) s = -1e30f;

        float mt = s;
        #pragma unroll
        for (int o = 16; o; o >>= 1) mt = fmaxf(mt, __shfl_xor_sync(0xffffffffu, mt, o));
        float mnew = fmaxf(m, mt);
        float corr = __expf(m - mnew);
        float p    = __expf(s - mnew);
        float ps   = p;
        #pragma unroll
        for (int o = 16; o; o >>= 1) ps += __shfl_xor_sync(0xffffffffu, ps, o);
        l = l * corr + ps;
        acc0 *= corr; acc1 *= corr;
        m = mnew;
        #pragma unroll
        for (int jj = 0; jj < 32; jj++) {
            float pj = __shfl_sync(0xffffffffu, p, jj);
            acc0 += pj * v_sh[jj][lane];
            acc1 += pj * v_sh[jj][lane + 32];
        }
        __syncthreads();
    }
    float invl = 1.f / l;
    size_t ob = ((size_t)(b * SS + iglob) * HH + h) * DK;
    O[ob + lane]      = acc0 * invl;
    O[ob + lane + 32] = acc1 * invl;
}

// ================= 3xBF16 split tensor-core GEMM ===========================
// C[M,N] = A[M,K] @ op(B) (+bias)(+residual), fp32 in/out.
// Split hi/lo bf16; products hi*hi + lo*hi + hi*lo (fp32 acc).
//   NT=false : B is [K,N] row-major
//   NT=true  : B is [N,K] row-major (use B^T)  -> LM head
// Tiles: 128x128x16; 512 threads, 16 warps (4x4), warp tile 32x32, mma m16n8k16.
#define BM 128
#define BN 128
#define BKT 16
#define ASTR 12     // 8 kpairs + 4 pad (uint32)  -> frag reads conflict-free
#define BSTR 136    // 128 cols + 8 pad           -> frag reads conflict-free

__device__ __forceinline__ void split2(float x0, float x1,
                                       unsigned &hi, unsigned &lo) {
    __nv_bfloat162 h = __floats2bfloat162_rn(x0, x1);
    float h0 = __bfloat162float(h.x);
    float h1 = __bfloat162float(h.y);
    __nv_bfloat162 l = __floats2bfloat162_rn(x0 - h0, x1 - h1);
    hi = *reinterpret_cast<unsigned*>(&h);
    lo = *reinterpret_cast<unsigned*>(&l);
}

#define BF16MMA(D, Ar, Br)                                                    \
    asm volatile(                                                             \
        "mma.sync.aligned.m16n8k16.row.col.f32.bf16.bf16.f32 "                \
        "{%0,%1,%2,%3}, {%4,%5,%6,%7}, {%8,%9}, {%0,%1,%2,%3};"               \
        : "+f"(D[0]), "+f"(D[1]), "+f"(D[2]), "+f"(D[3])                      \
        : "r"(Ar[0]), "r"(Ar[1]), "r"(Ar[2]), "r"(Ar[3]),                     \
          "r"(Br[0]), "r"(Br[1]))

template<bool NT>
__global__ __launch_bounds__(512)
void gemm_tc_kernel(const float* __restrict__ A, const float* __restrict__ B,
                    const float* __restrict__ bias, const float* __restrict__ res,
                    float* __restrict__ C, int Nd, int Kd) {
    __shared__ unsigned AsH[2][BM][ASTR];
    __shared__ unsigned AsL[2][BM][ASTR];
    __shared__ unsigned BsH[2][8][BSTR];
    __shared__ unsigned BsL[2][8][BSTR];

    const int t    = threadIdx.x;
    const int lane = t & 31;
    const int warp = t >> 5;             // 0..15
    const int wm   = warp >> 2;          // 0..3
    const int wn   = warp & 3;           // 0..3
    const int bm   = blockIdx.y * BM;
    const int bn   = blockIdx.x * BN;

    // A staging: one float4 per thread (128 rows x 4 kpair-groups)
    const int arow  = t >> 2;            // 0..127
    const int acol4 = (t & 3) * 4;       // k offset 0,4,8,12
    const int akp   = (t & 3) * 2;       // kpair base

    // B staging: thread owns one column, 2 kpairs (quarter of the 8)
    const int bcol  = t & 127;
    const int bq    = t >> 7;            // 0..3
    const bool bok  = NT || (bn + bcol < Nd);

    float acc[2][4][4] = {};
    float4 aR;
    float  bReg[4];

    const int nkt = Kd / BKT;

    auto g_load = [&](int kt) {
        const int k0 = kt * BKT;
        aR = *(const float4*)(A + (size_t)(bm + arow) * Kd + k0 + acol4);
        if (NT) {
            float4 e = *(const float4*)(B + (size_t)(bn + bcol) * Kd + k0 + bq * 4);
            bReg[0] = e.x; bReg[1] = e.y; bReg[2] = e.z; bReg[3] = e.w;
        } else {
            #pragma unroll
            for (int j = 0; j < 2; j++) {
                int kk = k0 + (bq * 2 + j) * 2;
                if (bok) {
                    bReg[2*j]   = B[(size_t)kk       * Nd + bn + bcol];
                    bReg[2*j+1] = B[(size_t)(kk + 1) * Nd + bn + bcol];
                } else {
                    bReg[2*j] = 0.f; bReg[2*j+1] = 0.f;
                }
            }
        }
    };
    auto s_store = [&](int buf) {
        split2(aR.x, aR.y, AsH[buf][arow][akp],     AsL[buf][arow][akp]);
        split2(aR.z, aR.w, AsH[buf][arow][akp + 1], AsL[buf][arow][akp + 1]);
        #pragma unroll
        for (int j = 0; j < 2; j++) {
            int kp = bq * 2 + j;
            split2(bReg[2*j], bReg[2*j+1], BsH[buf][kp][bcol], BsL[buf][kp][bcol]);
        }
    };

    g_load(0);
    s_store(0);
    __syncthreads();

    const int m0 = wm * 32;
    const int n0 = wn * 32;
    const int lq = lane >> 2;   // 0..7
    const int lr = lane & 3;    // 0..3

    for (int kt = 0; kt < nkt; kt++) {
        const int cur = kt & 1;
        if (kt + 1 < nkt) g_load(kt + 1);

        unsigned aH[2][4], aL[2][4], bH[4][2], bL[4][2];
        #pragma unroll
        for (int mi = 0; mi < 2; mi++) {
            int r = m0 + mi * 16 + lq;
            aH[mi][0] = AsH[cur][r    ][lr];     aH[mi][1] = AsH[cur][r + 8][lr];
            aH[mi][2] = AsH[cur][r    ][lr + 4]; aH[mi][3] = AsH[cur][r + 8][lr + 4];
            aL[mi][0] = AsL[cur][r    ][lr];     aL[mi][1] = AsL[cur][r + 8][lr];
            aL[mi][2] = AsL[cur][r    ][lr + 4]; aL[mi][3] = AsL[cur][r + 8][lr + 4];
        }
        #pragma unroll
        for (int ni = 0; ni < 4; ni++) {
            int c = n0 + ni * 8 + lq;
            bH[ni][0] = BsH[cur][lr][c]; bH[ni][1] = BsH[cur][lr + 4][c];
            bL[ni][0] = BsL[cur][lr][c]; bL[ni][1] = BsL[cur][lr + 4][c];
        }
        #pragma unroll
        for (int mi = 0; mi < 2; mi++)
            #pragma unroll
            for (int ni = 0; ni < 4; ni++) {
                BF16MMA(acc[mi][ni], aH[mi], bH[ni]);
                BF16MMA(acc[mi][ni], aL[mi], bH[ni]);
                BF16MMA(acc[mi][ni], aH[mi], bL[ni]);
            }

        if (kt + 1 < nkt) s_store((kt + 1) & 1);
        __syncthreads();
    }

    // ---- epilogue
    #pragma unroll
    for (int mi = 0; mi < 2; mi++) {
        int row = bm + m0 + mi * 16 + lq;
        #pragma unroll
        for (int ni = 0; ni < 4; ni++) {
            int col = bn + n0 + ni * 8 + lr * 2;
            if (col < Nd) {
                float v0 = acc[mi][ni][0], v1 = acc[mi][ni][1];
                float v2 = acc[mi][ni][2], v3 = acc[mi][ni][3];
                if (bias) {
                    float bx = bias[col], by = bias[col + 1];
                    v0 += bx; v1 += by; v2 += bx; v3 += by;
                }
                size_t o0 = (size_t)row * Nd + col;
                size_t o1 = (size_t)(row + 8) * Nd + col;
                if (res) {
                    v0 += res[o0]; v1 += res[o0 + 1];
                    v2 += res[o1]; v3 += res[o1 + 1];
                }
                C[o0] = v0; C[o0 + 1] = v1;
                C[o1] = v2; C[o1 + 1] = v3;
            }
        }
    }
}

// ---------------- silu(f1)*f2 -> f1 ----------------
__global__ void silumul_kernel(float* __restrict__ f1, const float* __restrict__ f2, int n) {
    int i = blockIdx.x * blockDim.x + threadIdx.x;
    if (i < n) {
        float a = f1[i];
        float s = a / (1.0f + __expf(-a));
        f1[i] = s * f2[i];
    }
}

// ---------------- host driver ----------------
extern "C" void kernel_launch(void* const* d_in, const int* in_sizes, int n_in,
                              void* d_out, int out_size) {
    const int*   tokens = (const int*)  d_in[0];
    const float* emb    = (const float*)d_in[1];
    const float* wq = (const float*)d_in[2];
    const float* bq = (const float*)d_in[3];
    const float* wk = (const float*)d_in[4];
    const float* bk = (const float*)d_in[5];
    const float* wv = (const float*)d_in[6];
    const float* bv = (const float*)d_in[7];
    const float* wo = (const float*)d_in[8];
    const float* bo = (const float*)d_in[9];
    const float* w1 = (const float*)d_in[10];
    const float* b1 = (const float*)d_in[11];
    const float* w2 = (const float*)d_in[12];
    const float* b2 = (const float*)d_in[13];
    const float* w3 = (const float*)d_in[14];
    const float* b3 = (const float*)d_in[15];
    const float* g1 = (const float*)d_in[16];
    const float* g2 = (const float*)d_in[17];
    const float* gpost = (const float*)d_in[18];
    const float* fcos  = (const float*)d_in[19];
    const float* fsin  = (const float*)d_in[20];
    float* out = (float*)d_out;

    float *x, *h, *q, *k, *v, *o, *f1, *f2;
    cudaGetSymbolAddress((void**)&x,  g_x);
    cudaGetSymbolAddress((void**)&h,  g_h);
    cudaGetSymbolAddress((void**)&q,  g_q);
    cudaGetSymbolAddress((void**)&k,  g_k);
    cudaGetSymbolAddress((void**)&v,  g_v);
    cudaGetSymbolAddress((void**)&o,  g_o);
    cudaGetSymbolAddress((void**)&f1, g_f1);
    cudaGetSymbolAddress((void**)&f2, g_f2);

    embed_kernel<<<MM, 256>>>(tokens, emb, x);

    const int KVN = KVH * DK;   // 512
    const int GY  = MM / BM;    // 32
    for (int l = 0; l < NL; l++) {
        rmsnorm_kernel<<<MM, 256>>>(x, g1 + (size_t)l * DD, h);

        gemm_tc_kernel<false><<<dim3(DD / BN, GY), 512>>>(
            h, wq + (size_t)l * DD * DD, bq + (size_t)l * DD, nullptr, q, DD, DD);
        gemm_tc_kernel<false><<<dim3(KVN / BN, GY), 512>>>(
            h, wk + (size_t)l * DD * KVN, bk + (size_t)l * KVN, nullptr, k, KVN, DD);
        gemm_tc_kernel<false><<<dim3(KVN / BN, GY), 512>>>(
            h, wv + (size_t)l * DD * KVN, bv + (size_t)l * KVN, nullptr, v, KVN, DD);

        int tq = MM * HH * 32,  tk = MM * KVH * 32;
        rope_kernel<<<(tq + 255) / 256, 256>>>(q, fcos, fsin, HH, tq);
        rope_kernel<<<(tk + 255) / 256, 256>>>(k, fcos, fsin, KVH, tk);

        attn_kernel<<<dim3(SS / ABM, HH, BB), dim3(32, 16)>>>(q, k, v, o);

        gemm_tc_kernel<false><<<dim3(DD / BN, GY), 512>>>(
            o, wo + (size_t)l * DD * DD, bo + (size_t)l * DD, x, x, DD, DD);

        rmsnorm_kernel<<<MM, 256>>>(x, g2 + (size_t)l * DD, h);

        int gnx = (FD + BN - 1) / BN;   // 22
        gemm_tc_kernel<false><<<dim3(gnx, GY), 512>>>(
            h, w1 + (size_t)l * DD * FD, b1 + (size_t)l * FD, nullptr, f1, FD, DD);
        gemm_tc_kernel<false><<<dim3(gnx, GY), 512>>>(
            h, w2 + (size_t)l * DD * FD, b2 + (size_t)l * FD, nullptr, f2, FD, DD);

        int nsm = MM * FD;
        silumul_kernel<<<(nsm + 255) / 256, 256>>>(f1, f2, nsm);

        gemm_tc_kernel<false><<<dim3(DD / BN, GY), 512>>>(
            f1, w3 + (size_t)l * FD * DD, b3 + (size_t)l * DD, x, x, DD, FD);
    }

    rmsnorm_kernel<<<MM, 256>>>(x, gpost, h);
    gemm_tc_kernel<true><<<dim3(VV / BN, GY), 512>>>(h, emb, nullptr, nullptr, out, VV, DD);
}

// round 5
// speedup vs baseline: 1.5341x; 1.5341x over previous
#include <cuda_runtime.h>
#include <cuda_bf16.h>
#include <math.h>

// Problem dims (fixed by the dataset)
#define BB   2
#define SS   2048
#define DD   1024
#define HH   16
#define KVH  8
#define DK   64
#define FD   2752
#define NL   4
#define VV   32000
#define MM   (BB*SS)          // 4096 token rows

// ---------------- scratch (device globals: no allocations allowed) ----------
__device__ float g_x [MM*DD];
__device__ float g_h [MM*DD];
__device__ float g_q [MM*DD];
__device__ float g_k [MM*(KVH*DK)];
__device__ float g_v [MM*(KVH*DK)];
__device__ float g_o [MM*DD];
__device__ float g_f1[(size_t)MM*FD];
__device__ float g_f2[(size_t)MM*FD];

// ---------------- embedding gather ----------------
__global__ void embed_kernel(const int* __restrict__ tokens,
                             const float* __restrict__ emb,
                             float* __restrict__ x) {
    int row = blockIdx.x;
    int tok = tokens[row];
    const float4* src = (const float4*)(emb + (size_t)tok * DD);
    float4*       dst = (float4*)(x + (size_t)row * DD);
    dst[threadIdx.x] = src[threadIdx.x];
}

// ---------------- rmsnorm ----------------
__global__ void rmsnorm_kernel(const float* __restrict__ x,
                               const float* __restrict__ g,
                               float* __restrict__ out) {
    int row = blockIdx.x;
    const float4* xr = (const float4*)(x + (size_t)row * DD);
    float4 v = xr[threadIdx.x];
    float ss = v.x*v.x + v.y*v.y + v.z*v.z + v.w*v.w;
    #pragma unroll
    for (int o = 16; o; o >>= 1) ss += __shfl_xor_sync(0xffffffffu, ss, o);
    __shared__ float red[8];
    if ((threadIdx.x & 31) == 0) red[threadIdx.x >> 5] = ss;
    __syncthreads();
    if (threadIdx.x < 8) {
        float r = red[threadIdx.x];
        #pragma unroll
        for (int o = 4; o; o >>= 1) r += __shfl_xor_sync(0xffu, r, o);
        if (threadIdx.x == 0) red[0] = r;
    }
    __syncthreads();
    float inv = rsqrtf(red[0] * (1.0f / DD) + 1e-6f);
    const float4* g4 = (const float4*)g;
    float4 gg = g4[threadIdx.x];
    float4 ov = make_float4(v.x*inv*gg.x, v.y*inv*gg.y, v.z*inv*gg.z, v.w*inv*gg.w);
    ((float4*)(out + (size_t)row * DD))[threadIdx.x] = ov;
}

// ---------------- rope (interleaved pairs) ----------------
__global__ void rope_kernel(float* __restrict__ buf,
                            const float* __restrict__ cosb,
                            const float* __restrict__ sinb,
                            int nheads, int total) {
    int idx = blockIdx.x * blockDim.x + threadIdx.x;
    if (idx >= total) return;
    int p    = idx & 31;
    int hrow = idx >> 5;
    int row  = hrow / nheads;
    int s    = row & (SS - 1);
    float c  = cosb[s * 32 + p];
    float sn = sinb[s * 32 + p];
    float* base = buf + (size_t)hrow * DK + p * 2;
    float xr = base[0], xi = base[1];
    base[0] = xr * c - xi * sn;
    base[1] = xr * sn + xi * c;
}

// ---------------- bf16 split helper ----------------
__device__ __forceinline__ void split2(float x0, float x1,
                                       unsigned &hi, unsigned &lo) {
    __nv_bfloat162 h = __floats2bfloat162_rn(x0, x1);
    float h0 = __bfloat162float(h.x);
    float h1 = __bfloat162float(h.y);
    __nv_bfloat162 l = __floats2bfloat162_rn(x0 - h0, x1 - h1);
    hi = *reinterpret_cast<unsigned*>(&h);
    lo = *reinterpret_cast<unsigned*>(&l);
}

#define BF16MMA(D, Ar, Br)                                                    \
    asm volatile(                                                             \
        "mma.sync.aligned.m16n8k16.row.col.f32.bf16.bf16.f32 "                \
        "{%0,%1,%2,%3}, {%4,%5,%6,%7}, {%8,%9}, {%0,%1,%2,%3};"               \
        : "+f"(D[0]), "+f"(D[1]), "+f"(D[2]), "+f"(D[3])                      \
        : "r"(Ar[0]), "r"(Ar[1]), "r"(Ar[2]), "r"(Ar[3]),                     \
          "r"(Br[0]), "r"(Br[1]))

// ======== flash attention v2, tensor-core, 3xBF16 split, causal, GQA =======
// block: 128 threads (4 warps), 64 q-rows per block, 64-key tiles.
// Q·K^T and P·V both on mma.m16n8k16 with hi/lo error compensation.
#define KSTR 72   // [dpair|keypair][64] rows padded to 72 -> conflict-free frags
__global__ __launch_bounds__(128)
void attn_tc_kernel(const float* __restrict__ Q, const float* __restrict__ K,
                    const float* __restrict__ V, float* __restrict__ O) {
    __shared__ unsigned KsH[32][KSTR], KsL[32][KSTR];
    __shared__ unsigned VsH[32][KSTR], VsL[32][KSTR];

    const int qb   = gridDim.x - 1 - blockIdx.x;   // heavy blocks first
    const int h    = blockIdx.y;
    const int b    = blockIdx.z;
    const int kh   = h >> 1;                       // n_rep = 2
    const int t    = threadIdx.x;
    const int lane = t & 31;
    const int w    = t >> 5;                       // warp: 16 q-rows each
    const int lq   = lane >> 2;                    // 0..7
    const int lr   = lane & 3;                     // 0..3

    // ---- Q fragments (resident, loaded once, scaled by 1/8) ----
    unsigned qaH[4][4], qaL[4][4];
    {
        const int r0 = qb * 64 + w * 16 + lq;
        const float* q0p = Q + ((size_t)(b * SS + r0) * HH + h) * DK;
        const float* q1p = q0p + (size_t)8 * HH * DK;
        #pragma unroll
        for (int kb = 0; kb < 4; kb++) {
            float2 v0 = *(const float2*)(q0p + kb * 16 + 2 * lr);
            float2 v1 = *(const float2*)(q1p + kb * 16 + 2 * lr);
            float2 v2 = *(const float2*)(q0p + kb * 16 + 8 + 2 * lr);
            float2 v3 = *(const float2*)(q1p + kb * 16 + 8 + 2 * lr);
            split2(v0.x * 0.125f, v0.y * 0.125f, qaH[kb][0], qaL[kb][0]);
            split2(v1.x * 0.125f, v1.y * 0.125f, qaH[kb][1], qaL[kb][1]);
            split2(v2.x * 0.125f, v2.y * 0.125f, qaH[kb][2], qaL[kb][2]);
            split2(v3.x * 0.125f, v3.y * 0.125f, qaH[kb][3], qaL[kb][3]);
        }
    }

    float acc[8][4] = {};
    float m0 = -1e30f, m1 = -1e30f, l0 = 0.f, l1 = 0.f;

    const int ntiles = qb + 1;
    for (int kt = 0; kt < ntiles; kt++) {
        const int kbase = kt * 64;
        if (kt) __syncthreads();
        // ---- stage K: KsH/L[dpair][key] ----
        {
            int krow = t >> 1, half = t & 1;
            const float* kp_ = K + ((size_t)(b * SS + kbase + krow) * KVH + kh) * DK + half * 32;
            #pragma unroll
            for (int i = 0; i < 8; i++) {
                float4 kv = ((const float4*)kp_)[i];
                int dp = half * 16 + i * 2;
                split2(kv.x, kv.y, KsH[dp][krow],     KsL[dp][krow]);
                split2(kv.z, kv.w, KsH[dp + 1][krow], KsL[dp + 1][krow]);
            }
        }
        // ---- stage V: VsH/L[keypair][d] (pairs of key rows) ----
        {
            int kp2 = t >> 2, q4 = t & 3;
            const float* vr0 = V + ((size_t)(b * SS + kbase + 2 * kp2) * KVH + kh) * DK + q4 * 16;
            const float* vr1 = vr0 + (size_t)KVH * DK;
            #pragma unroll
            for (int i = 0; i < 4; i++) {
                float4 a = ((const float4*)vr0)[i];
                float4 c = ((const float4*)vr1)[i];
                int d = q4 * 16 + i * 4;
                split2(a.x, c.x, VsH[kp2][d],     VsL[kp2][d]);
                split2(a.y, c.y, VsH[kp2][d + 1], VsL[kp2][d + 1]);
                split2(a.z, c.z, VsH[kp2][d + 2], VsL[kp2][d + 2]);
                split2(a.w, c.w, VsH[kp2][d + 3], VsL[kp2][d + 3]);
            }
        }
        __syncthreads();

        // ---- S = Q K^T (16x64 per warp), split 3-mma ----
        float s[8][4] = {};
        #pragma unroll
        for (int kb = 0; kb < 4; kb++) {
            unsigned kfH[8][2], kfL[8][2];
            #pragma unroll
            for (int ni = 0; ni < 8; ni++) {
                kfH[ni][0] = KsH[kb * 8 + lr][ni * 8 + lq];
                kfH[ni][1] = KsH[kb * 8 + lr + 4][ni * 8 + lq];
                kfL[ni][0] = KsL[kb * 8 + lr][ni * 8 + lq];
                kfL[ni][1] = KsL[kb * 8 + lr + 4][ni * 8 + lq];
            }
            #pragma unroll
            for (int ni = 0; ni < 8; ni++) {
                BF16MMA(s[ni], qaH[kb], kfH[ni]);
                BF16MMA(s[ni], qaL[kb], kfH[ni]);
                BF16MMA(s[ni], qaH[kb], kfL[ni]);
            }
        }

        // ---- causal mask (diagonal tile only) ----
        if (kt == qb) {
            int row0 = qb * 64 + w * 16 + lq;
            #pragma unroll
            for (int ni = 0; ni < 8; ni++) {
                int col = kbase + ni * 8 + 2 * lr;
                if (col     > row0)     s[ni][0] = -1e30f;
                if (col + 1 > row0)     s[ni][1] = -1e30f;
                if (col     > row0 + 8) s[ni][2] = -1e30f;
                if (col + 1 > row0 + 8) s[ni][3] = -1e30f;
            }
        }

        // ---- online softmax ----
        float mt0 = -1e30f, mt1 = -1e30f;
        #pragma unroll
        for (int ni = 0; ni < 8; ni++) {
            mt0 = fmaxf(mt0, fmaxf(s[ni][0], s[ni][1]));
            mt1 = fmaxf(mt1, fmaxf(s[ni][2], s[ni][3]));
        }
        mt0 = fmaxf(mt0, __shfl_xor_sync(0xffffffffu, mt0, 1));
        mt0 = fmaxf(mt0, __shfl_xor_sync(0xffffffffu, mt0, 2));
        mt1 = fmaxf(mt1, __shfl_xor_sync(0xffffffffu, mt1, 1));
        mt1 = fmaxf(mt1, __shfl_xor_sync(0xffffffffu, mt1, 2));
        float mn0 = fmaxf(m0, mt0), mn1 = fmaxf(m1, mt1);
        float c0 = __expf(m0 - mn0), c1 = __expf(m1 - mn1);
        m0 = mn0; m1 = mn1;
        float rs0 = 0.f, rs1 = 0.f;
        #pragma unroll
        for (int ni = 0; ni < 8; ni++) {
            s[ni][0] = __expf(s[ni][0] - mn0);
            s[ni][1] = __expf(s[ni][1] - mn0);
            s[ni][2] = __expf(s[ni][2] - mn1);
            s[ni][3] = __expf(s[ni][3] - mn1);
            rs0 += s[ni][0] + s[ni][1];
            rs1 += s[ni][2] + s[ni][3];
        }
        rs0 += __shfl_xor_sync(0xffffffffu, rs0, 1);
        rs0 += __shfl_xor_sync(0xffffffffu, rs0, 2);
        rs1 += __shfl_xor_sync(0xffffffffu, rs1, 1);
        rs1 += __shfl_xor_sync(0xffffffffu, rs1, 2);
        l0 = l0 * c0 + rs0;
        l1 = l1 * c1 + rs1;
        #pragma unroll
        for (int dn = 0; dn < 8; dn++) {
            acc[dn][0] *= c0; acc[dn][1] *= c0;
            acc[dn][2] *= c1; acc[dn][3] *= c1;
        }

        // ---- O += P V (split 3-mma; P from S c-frag -> a-frag identity) ----
        #pragma unroll
        for (int kb = 0; kb < 4; kb++) {
            unsigned aPH[4], aPL[4];
            split2(s[2*kb][0],   s[2*kb][1],   aPH[0], aPL[0]);
            split2(s[2*kb][2],   s[2*kb][3],   aPH[1], aPL[1]);
            split2(s[2*kb+1][0], s[2*kb+1][1], aPH[2], aPL[2]);
            split2(s[2*kb+1][2], s[2*kb+1][3], aPH[3], aPL[3]);
            #pragma unroll
            for (int dn = 0; dn < 8; dn++) {
                unsigned vfH[2], vfL[2];
                vfH[0] = VsH[kb * 8 + lr][dn * 8 + lq];
                vfH[1] = VsH[kb * 8 + lr + 4][dn * 8 + lq];
                vfL[0] = VsL[kb * 8 + lr][dn * 8 + lq];
                vfL[1] = VsL[kb * 8 + lr + 4][dn * 8 + lq];
                BF16MMA(acc[dn], aPH, vfH);
                BF16MMA(acc[dn], aPL, vfH);
                BF16MMA(acc[dn], aPH, vfL);
            }
        }
    }

    // ---- epilogue ----
    float inv0 = 1.f / l0, inv1 = 1.f / l1;
    int row0 = qb * 64 + w * 16 + lq;
    float* o0 = O + ((size_t)(b * SS + row0) * HH + h) * DK;
    float* o1 = o0 + (size_t)8 * HH * DK;
    #pragma unroll
    for (int dn = 0; dn < 8; dn++) {
        int d = dn * 8 + 2 * lr;
        *(float2*)(o0 + d) = make_float2(acc[dn][0] * inv0, acc[dn][1] * inv0);
        *(float2*)(o1 + d) = make_float2(acc[dn][2] * inv1, acc[dn][3] * inv1);
    }
}

// ================= 3xBF16 split tensor-core GEMM (round-3 config) ==========
#define BM 128
#define BN 128
#define BKT 16
#define ASTR 12
#define BSTR 136

template<bool NT>
__global__ __launch_bounds__(256)
void gemm_tc_kernel(const float* __restrict__ A, const float* __restrict__ B,
                    const float* __restrict__ bias, const float* __restrict__ res,
                    float* __restrict__ C, int Nd, int Kd) {
    __shared__ unsigned AsH[2][BM][ASTR];
    __shared__ unsigned AsL[2][BM][ASTR];
    __shared__ unsigned BsH[2][8][BSTR];
    __shared__ unsigned BsL[2][8][BSTR];

    const int t    = threadIdx.x;
    const int lane = t & 31;
    const int warp = t >> 5;
    const int wm   = warp >> 2;
    const int wn   = warp & 3;
    const int bm   = blockIdx.y * BM;
    const int bn   = blockIdx.x * BN;

    const int arow  = t >> 2;
    const int acol4 = (t & 3) * 4;
    const int akp   = (t & 3) * 2;

    const int bcol  = t & 127;
    const int bhalf = t >> 7;
    const bool bok  = NT || (bn + bcol < Nd);

    float acc[4][4][4] = {};
    float4 aR0, aR1;
    float  bReg[8];

    const int nkt = Kd / BKT;

    auto g_load = [&](int kt) {
        const int k0 = kt * BKT;
        aR0 = *(const float4*)(A + (size_t)(bm + arow)      * Kd + k0 + acol4);
        aR1 = *(const float4*)(A + (size_t)(bm + arow + 64) * Kd + k0 + acol4);
        if (NT) {
            const float* ep = B + (size_t)(bn + bcol) * Kd + k0 + bhalf * 8;
            float4 e0 = *(const float4*)(ep);
            float4 e1 = *(const float4*)(ep + 4);
            bReg[0] = e0.x; bReg[1] = e0.y; bReg[2] = e0.z; bReg[3] = e0.w;
            bReg[4] = e1.x; bReg[5] = e1.y; bReg[6] = e1.z; bReg[7] = e1.w;
        } else {
            #pragma unroll
            for (int j = 0; j < 4; j++) {
                int kk = k0 + (bhalf * 4 + j) * 2;
                if (bok) {
                    bReg[2*j]   = B[(size_t)kk       * Nd + bn + bcol];
                    bReg[2*j+1] = B[(size_t)(kk + 1) * Nd + bn + bcol];
                } else {
                    bReg[2*j] = 0.f; bReg[2*j+1] = 0.f;
                }
            }
        }
    };
    auto s_store = [&](int buf) {
        split2(aR0.x, aR0.y, AsH[buf][arow][akp],        AsL[buf][arow][akp]);
        split2(aR0.z, aR0.w, AsH[buf][arow][akp + 1],    AsL[buf][arow][akp + 1]);
        split2(aR1.x, aR1.y, AsH[buf][arow+64][akp],     AsL[buf][arow+64][akp]);
        split2(aR1.z, aR1.w, AsH[buf][arow+64][akp + 1], AsL[buf][arow+64][akp + 1]);
        #pragma unroll
        for (int j = 0; j < 4; j++) {
            int kp = bhalf * 4 + j;
            split2(bReg[2*j], bReg[2*j+1], BsH[buf][kp][bcol], BsL[buf][kp][bcol]);
        }
    };

    g_load(0);
    s_store(0);
    __syncthreads();

    const int m0 = wm * 64;
    const int n0 = wn * 32;
    const int lq = lane >> 2;
    const int lr = lane & 3;

    for (int kt = 0; kt < nkt; kt++) {
        const int cur = kt & 1;
        if (kt + 1 < nkt) g_load(kt + 1);

        unsigned aH[4][4], aL[4][4], bH[4][2], bL[4][2];
        #pragma unroll
        for (int mi = 0; mi < 4; mi++) {
            int r = m0 + mi * 16 + lq;
            aH[mi][0] = AsH[cur][r    ][lr];     aH[mi][1] = AsH[cur][r + 8][lr];
            aH[mi][2] = AsH[cur][r    ][lr + 4]; aH[mi][3] = AsH[cur][r + 8][lr + 4];
            aL[mi][0] = AsL[cur][r    ][lr];     aL[mi][1] = AsL[cur][r + 8][lr];
            aL[mi][2] = AsL[cur][r    ][lr + 4]; aL[mi][3] = AsL[cur][r + 8][lr + 4];
        }
        #pragma unroll
        for (int ni = 0; ni < 4; ni++) {
            int c = n0 + ni * 8 + lq;
            bH[ni][0] = BsH[cur][lr][c]; bH[ni][1] = BsH[cur][lr + 4][c];
            bL[ni][0] = BsL[cur][lr][c]; bL[ni][1] = BsL[cur][lr + 4][c];
        }
        #pragma unroll
        for (int mi = 0; mi < 4; mi++)
            #pragma unroll
            for (int ni = 0; ni < 4; ni++) {
                BF16MMA(acc[mi][ni], aH[mi], bH[ni]);
                BF16MMA(acc[mi][ni], aL[mi], bH[ni]);
                BF16MMA(acc[mi][ni], aH[mi], bL[ni]);
            }

        if (kt + 1 < nkt) s_store((kt + 1) & 1);
        __syncthreads();
    }

    #pragma unroll
    for (int mi = 0; mi < 4; mi++) {
        int row = bm + m0 + mi * 16 + lq;
        #pragma unroll
        for (int ni = 0; ni < 4; ni++) {
            int col = bn + n0 + ni * 8 + lr * 2;
            if (col < Nd) {
                float v0 = acc[mi][ni][0], v1 = acc[mi][ni][1];
                float v2 = acc[mi][ni][2], v3 = acc[mi][ni][3];
                if (bias) {
                    float bx = bias[col], by = bias[col + 1];
                    v0 += bx; v1 += by; v2 += bx; v3 += by;
                }
                size_t o0 = (size_t)row * Nd + col;
                size_t o1 = (size_t)(row + 8) * Nd + col;
                if (res) {
                    v0 += res[o0]; v1 += res[o0 + 1];
                    v2 += res[o1]; v3 += res[o1 + 1];
                }
                C[o0] = v0; C[o0 + 1] = v1;
                C[o1] = v2; C[o1 + 1] = v3;
            }
        }
    }
}

// ---------------- silu(f1)*f2 -> f1 ----------------
__global__ void silumul_kernel(float* __restrict__ f1, const float* __restrict__ f2, int n) {
    int i = blockIdx.x * blockDim.x + threadIdx.x;
    if (i < n) {
        float a = f1[i];
        float s = a / (1.0f + __expf(-a));
        f1[i] = s * f2[i];
    }
}

// ---------------- host driver ----------------
extern "C" void kernel_launch(void* const* d_in, const int* in_sizes, int n_in,
                              void* d_out, int out_size) {
    const int*   tokens = (const int*)  d_in[0];
    const float* emb    = (const float*)d_in[1];
    const float* wq = (const float*)d_in[2];
    const float* bq = (const float*)d_in[3];
    const float* wk = (const float*)d_in[4];
    const float* bk = (const float*)d_in[5];
    const float* wv = (const float*)d_in[6];
    const float* bv = (const float*)d_in[7];
    const float* wo = (const float*)d_in[8];
    const float* bo = (const float*)d_in[9];
    const float* w1 = (const float*)d_in[10];
    const float* b1 = (const float*)d_in[11];
    const float* w2 = (const float*)d_in[12];
    const float* b2 = (const float*)d_in[13];
    const float* w3 = (const float*)d_in[14];
    const float* b3 = (const float*)d_in[15];
    const float* g1 = (const float*)d_in[16];
    const float* g2 = (const float*)d_in[17];
    const float* gpost = (const float*)d_in[18];
    const float* fcos  = (const float*)d_in[19];
    const float* fsin  = (const float*)d_in[20];
    float* out = (float*)d_out;

    float *x, *h, *q, *k, *v, *o, *f1, *f2;
    cudaGetSymbolAddress((void**)&x,  g_x);
    cudaGetSymbolAddress((void**)&h,  g_h);
    cudaGetSymbolAddress((void**)&q,  g_q);
    cudaGetSymbolAddress((void**)&k,  g_k);
    cudaGetSymbolAddress((void**)&v,  g_v);
    cudaGetSymbolAddress((void**)&o,  g_o);
    cudaGetSymbolAddress((void**)&f1, g_f1);
    cudaGetSymbolAddress((void**)&f2, g_f2);

    embed_kernel<<<MM, 256>>>(tokens, emb, x);

    const int KVN = KVH * DK;   // 512
    const int GY  = MM / BM;    // 32
    for (int l = 0; l < NL; l++) {
        rmsnorm_kernel<<<MM, 256>>>(x, g1 + (size_t)l * DD, h);

        gemm_tc_kernel<false><<<dim3(DD / BN, GY), 256>>>(
            h, wq + (size_t)l * DD * DD, bq + (size_t)l * DD, nullptr, q, DD, DD);
        gemm_tc_kernel<false><<<dim3(KVN / BN, GY), 256>>>(
            h, wk + (size_t)l * DD * KVN, bk + (size_t)l * KVN, nullptr, k, KVN, DD);
        gemm_tc_kernel<false><<<dim3(KVN / BN, GY), 256>>>(
            h, wv + (size_t)l * DD * KVN, bv + (size_t)l * KVN, nullptr, v, KVN, DD);

        int tq = MM * HH * 32,  tk = MM * KVH * 32;
        rope_kernel<<<(tq + 255) / 256, 256>>>(q, fcos, fsin, HH, tq);
        rope_kernel<<<(tk + 255) / 256, 256>>>(k, fcos, fsin, KVH, tk);

        attn_tc_kernel<<<dim3(SS / 64, HH, BB), 128>>>(q, k, v, o);

        gemm_tc_kernel<false><<<dim3(DD / BN, GY), 256>>>(
            o, wo + (size_t)l * DD * DD, bo + (size_t)l * DD, x, x, DD, DD);

        rmsnorm_kernel<<<MM, 256>>>(x, g2 + (size_t)l * DD, h);

        int gnx = (FD + BN - 1) / BN;   // 22
        gemm_tc_kernel<false><<<dim3(gnx, GY), 256>>>(
            h, w1 + (size_t)l * DD * FD, b1 + (size_t)l * FD, nullptr, f1, FD, DD);
        gemm_tc_kernel<false><<<dim3(gnx, GY), 256>>>(
            h, w2 + (size_t)l * DD * FD, b2 + (size_t)l * FD, nullptr, f2, FD, DD);

        int nsm = MM * FD;
        silumul_kernel<<<(nsm + 255) / 256, 256>>>(f1, f2, nsm);

        gemm_tc_kernel<false><<<dim3(DD / BN, GY), 256>>>(
            f1, w3 + (size_t)l * FD * DD, b3 + (size_t)l * DD, x, x, DD, FD);
    }

    rmsnorm_kernel<<<MM, 256>>>(x, gpost, h);
    gemm_tc_kernel<true><<<dim3(VV / BN, GY), 256>>>(h, emb, nullptr, nullptr, out, VV, DD);
}

// round 7
// speedup vs baseline: 1.7483x; 1.1396x over previous
#include <cuda_runtime.h>
#include <cuda_bf16.h>
#include <math.h>
#include <stdint.h>

// Problem dims (fixed by the dataset)
#define BB   2
#define SS   2048
#define DD   1024
#define HH   16
#define KVH  8
#define DK   64
#define FD   2752
#define NL   4
#define VV   32000
#define MM   (BB*SS)          // 4096 token rows

// ---------------- scratch (device globals: no allocations allowed) ----------
__device__ float g_x [MM*DD];
__device__ float g_h [MM*DD];
__device__ float g_q [MM*DD];
__device__ float g_k [MM*(KVH*DK)];
__device__ float g_v [MM*(KVH*DK)];
__device__ float g_o [MM*DD];
__device__ float g_f1[(size_t)MM*FD];
__device__ float g_f2[(size_t)MM*FD];

// ---------------- embedding gather ----------------
__global__ void embed_kernel(const int* __restrict__ tokens,
                             const float* __restrict__ emb,
                             float* __restrict__ x) {
    int row = blockIdx.x;
    int tok = tokens[row];
    const float4* src = (const float4*)(emb + (size_t)tok * DD);
    float4*       dst = (float4*)(x + (size_t)row * DD);
    dst[threadIdx.x] = src[threadIdx.x];
}

// ---------------- rmsnorm ----------------
__global__ void rmsnorm_kernel(const float* __restrict__ x,
                               const float* __restrict__ g,
                               float* __restrict__ out) {
    int row = blockIdx.x;
    const float4* xr = (const float4*)(x + (size_t)row * DD);
    float4 v = xr[threadIdx.x];
    float ss = v.x*v.x + v.y*v.y + v.z*v.z + v.w*v.w;
    #pragma unroll
    for (int o = 16; o; o >>= 1) ss += __shfl_xor_sync(0xffffffffu, ss, o);
    __shared__ float red[8];
    if ((threadIdx.x & 31) == 0) red[threadIdx.x >> 5] = ss;
    __syncthreads();
    if (threadIdx.x < 8) {
        float r = red[threadIdx.x];
        #pragma unroll
        for (int o = 4; o; o >>= 1) r += __shfl_xor_sync(0xffu, r, o);
        if (threadIdx.x == 0) red[0] = r;
    }
    __syncthreads();
    float inv = rsqrtf(red[0] * (1.0f / DD) + 1e-6f);
    const float4* g4 = (const float4*)g;
    float4 gg = g4[threadIdx.x];
    float4 ov = make_float4(v.x*inv*gg.x, v.y*inv*gg.y, v.z*inv*gg.z, v.w*inv*gg.w);
    ((float4*)(out + (size_t)row * DD))[threadIdx.x] = ov;
}

// ---------------- rope (interleaved pairs) ----------------
__global__ void rope_kernel(float* __restrict__ buf,
                            const float* __restrict__ cosb,
                            const float* __restrict__ sinb,
                            int nheads, int total) {
    int idx = blockIdx.x * blockDim.x + threadIdx.x;
    if (idx >= total) return;
    int p    = idx & 31;
    int hrow = idx >> 5;
    int row  = hrow / nheads;
    int s    = row & (SS - 1);
    float c  = cosb[s * 32 + p];
    float sn = sinb[s * 32 + p];
    float* base = buf + (size_t)hrow * DK + p * 2;
    float xr = base[0], xi = base[1];
    base[0] = xr * c - xi * sn;
    base[1] = xr * sn + xi * c;
}

// ---------------- bf16 split helper ----------------
__device__ __forceinline__ void split2(float x0, float x1,
                                       unsigned &hi, unsigned &lo) {
    __nv_bfloat162 h = __floats2bfloat162_rn(x0, x1);
    float h0 = __bfloat162float(h.x);
    float h1 = __bfloat162float(h.y);
    __nv_bfloat162 l = __floats2bfloat162_rn(x0 - h0, x1 - h1);
    hi = *reinterpret_cast<unsigned*>(&h);
    lo = *reinterpret_cast<unsigned*>(&l);
}

#define BF16MMA(D, Ar, Br)                                                    \
    asm volatile(                                                             \
        "mma.sync.aligned.m16n8k16.row.col.f32.bf16.bf16.f32 "                \
        "{%0,%1,%2,%3}, {%4,%5,%6,%7}, {%8,%9}, {%0,%1,%2,%3};"               \
        : "+f"(D[0]), "+f"(D[1]), "+f"(D[2]), "+f"(D[3])                      \
        : "r"(Ar[0]), "r"(Ar[1]), "r"(Ar[2]), "r"(Ar[3]),                     \
          "r"(Br[0]), "r"(Br[1]))

#define LDSM4(R0, R1, R2, R3, ADDR)                                           \
    asm volatile("ldmatrix.sync.aligned.m8n8.x4.shared.b16 {%0,%1,%2,%3}, [%4];" \
        : "=r"(R0), "=r"(R1), "=r"(R2), "=r"(R3) : "r"(ADDR))

// ======== flash attention v2, tensor-core, 3xBF16 split, causal, GQA =======
#define KSTR 72
__global__ __launch_bounds__(128)
void attn_tc_kernel(const float* __restrict__ Q, const float* __restrict__ K,
                    const float* __restrict__ V, float* __restrict__ O) {
    __shared__ unsigned KsH[32][KSTR], KsL[32][KSTR];
    __shared__ unsigned VsH[32][KSTR], VsL[32][KSTR];

    const int qb   = gridDim.x - 1 - blockIdx.x;
    const int h    = blockIdx.y;
    const int b    = blockIdx.z;
    const int kh   = h >> 1;
    const int t    = threadIdx.x;
    const int lane = t & 31;
    const int w    = t >> 5;
    const int lq   = lane >> 2;
    const int lr   = lane & 3;

    unsigned qaH[4][4], qaL[4][4];
    {
        const int r0 = qb * 64 + w * 16 + lq;
        const float* q0p = Q + ((size_t)(b * SS + r0) * HH + h) * DK;
        const float* q1p = q0p + (size_t)8 * HH * DK;
        #pragma unroll
        for (int kb = 0; kb < 4; kb++) {
            float2 v0 = *(const float2*)(q0p + kb * 16 + 2 * lr);
            float2 v1 = *(const float2*)(q1p + kb * 16 + 2 * lr);
            float2 v2 = *(const float2*)(q0p + kb * 16 + 8 + 2 * lr);
            float2 v3 = *(const float2*)(q1p + kb * 16 + 8 + 2 * lr);
            split2(v0.x * 0.125f, v0.y * 0.125f, qaH[kb][0], qaL[kb][0]);
            split2(v1.x * 0.125f, v1.y * 0.125f, qaH[kb][1], qaL[kb][1]);
            split2(v2.x * 0.125f, v2.y * 0.125f, qaH[kb][2], qaL[kb][2]);
            split2(v3.x * 0.125f, v3.y * 0.125f, qaH[kb][3], qaL[kb][3]);
        }
    }

    float acc[8][4] = {};
    float m0 = -1e30f, m1 = -1e30f, l0 = 0.f, l1 = 0.f;

    const int ntiles = qb + 1;
    for (int kt = 0; kt < ntiles; kt++) {
        const int kbase = kt * 64;
        if (kt) __syncthreads();
        {
            int krow = t >> 1, hf = t & 1;
            const float* kp_ = K + ((size_t)(b * SS + kbase + krow) * KVH + kh) * DK + hf * 32;
            #pragma unroll
            for (int i = 0; i < 8; i++) {
                float4 kv = ((const float4*)kp_)[i];
                int dp = hf * 16 + i * 2;
                split2(kv.x, kv.y, KsH[dp][krow],     KsL[dp][krow]);
                split2(kv.z, kv.w, KsH[dp + 1][krow], KsL[dp + 1][krow]);
            }
        }
        {
            int kp2 = t >> 2, q4 = t & 3;
            const float* vr0 = V + ((size_t)(b * SS + kbase + 2 * kp2) * KVH + kh) * DK + q4 * 16;
            const float* vr1 = vr0 + (size_t)KVH * DK;
            #pragma unroll
            for (int i = 0; i < 4; i++) {
                float4 a = ((const float4*)vr0)[i];
                float4 c = ((const float4*)vr1)[i];
                int d = q4 * 16 + i * 4;
                split2(a.x, c.x, VsH[kp2][d],     VsL[kp2][d]);
                split2(a.y, c.y, VsH[kp2][d + 1], VsL[kp2][d + 1]);
                split2(a.z, c.z, VsH[kp2][d + 2], VsL[kp2][d + 2]);
                split2(a.w, c.w, VsH[kp2][d + 3], VsL[kp2][d + 3]);
            }
        }
        __syncthreads();

        float s[8][4] = {};
        #pragma unroll
        for (int kb = 0; kb < 4; kb++) {
            unsigned kfH[8][2], kfL[8][2];
            #pragma unroll
            for (int ni = 0; ni < 8; ni++) {
                kfH[ni][0] = KsH[kb * 8 + lr][ni * 8 + lq];
                kfH[ni][1] = KsH[kb * 8 + lr + 4][ni * 8 + lq];
                kfL[ni][0] = KsL[kb * 8 + lr][ni * 8 + lq];
                kfL[ni][1] = KsL[kb * 8 + lr + 4][ni * 8 + lq];
            }
            #pragma unroll
            for (int ni = 0; ni < 8; ni++) {
                BF16MMA(s[ni], qaH[kb], kfH[ni]);
                BF16MMA(s[ni], qaL[kb], kfH[ni]);
                BF16MMA(s[ni], qaH[kb], kfL[ni]);
            }
        }

        if (kt == qb) {
            int row0 = qb * 64 + w * 16 + lq;
            #pragma unroll
            for (int ni = 0; ni < 8; ni++) {
                int col = kbase + ni * 8 + 2 * lr;
                if (col     > row0)     s[ni][0] = -1e30f;
                if (col + 1 > row0)     s[ni][1] = -1e30f;
                if (col     > row0 + 8) s[ni][2] = -1e30f;
                if (col + 1 > row0 + 8) s[ni][3] = -1e30f;
            }
        }

        float mt0 = -1e30f, mt1 = -1e30f;
        #pragma unroll
        for (int ni = 0; ni < 8; ni++) {
            mt0 = fmaxf(mt0, fmaxf(s[ni][0], s[ni][1]));
            mt1 = fmaxf(mt1, fmaxf(s[ni][2], s[ni][3]));
        }
        mt0 = fmaxf(mt0, __shfl_xor_sync(0xffffffffu, mt0, 1));
        mt0 = fmaxf(mt0, __shfl_xor_sync(0xffffffffu, mt0, 2));
        mt1 = fmaxf(mt1, __shfl_xor_sync(0xffffffffu, mt1, 1));
        mt1 = fmaxf(mt1, __shfl_xor_sync(0xffffffffu, mt1, 2));
        float mn0 = fmaxf(m0, mt0), mn1 = fmaxf(m1, mt1);
        float c0 = __expf(m0 - mn0), c1 = __expf(m1 - mn1);
        m0 = mn0; m1 = mn1;
        float rs0 = 0.f, rs1 = 0.f;
        #pragma unroll
        for (int ni = 0; ni < 8; ni++) {
            s[ni][0] = __expf(s[ni][0] - mn0);
            s[ni][1] = __expf(s[ni][1] - mn0);
            s[ni][2] = __expf(s[ni][2] - mn1);
            s[ni][3] = __expf(s[ni][3] - mn1);
            rs0 += s[ni][0] + s[ni][1];
            rs1 += s[ni][2] + s[ni][3];
        }
        rs0 += __shfl_xor_sync(0xffffffffu, rs0, 1);
        rs0 += __shfl_xor_sync(0xffffffffu, rs0, 2);
        rs1 += __shfl_xor_sync(0xffffffffu, rs1, 1);
        rs1 += __shfl_xor_sync(0xffffffffu, rs1, 2);
        l0 = l0 * c0 + rs0;
        l1 = l1 * c1 + rs1;
        #pragma unroll
        for (int dn = 0; dn < 8; dn++) {
            acc[dn][0] *= c0; acc[dn][1] *= c0;
            acc[dn][2] *= c1; acc[dn][3] *= c1;
        }

        #pragma unroll
        for (int kb = 0; kb < 4; kb++) {
            unsigned aPH[4], aPL[4];
            split2(s[2*kb][0],   s[2*kb][1],   aPH[0], aPL[0]);
            split2(s[2*kb][2],   s[2*kb][3],   aPH[1], aPL[1]);
            split2(s[2*kb+1][0], s[2*kb+1][1], aPH[2], aPL[2]);
            split2(s[2*kb+1][2], s[2*kb+1][3], aPH[3], aPL[3]);
            #pragma unroll
            for (int dn = 0; dn < 8; dn++) {
                unsigned vfH[2], vfL[2];
                vfH[0] = VsH[kb * 8 + lr][dn * 8 + lq];
                vfH[1] = VsH[kb * 8 + lr + 4][dn * 8 + lq];
                vfL[0] = VsL[kb * 8 + lr][dn * 8 + lq];
                vfL[1] = VsL[kb * 8 + lr + 4][dn * 8 + lq];
                BF16MMA(acc[dn], aPH, vfH);
                BF16MMA(acc[dn], aPL, vfH);
                BF16MMA(acc[dn], aPH, vfL);
            }
        }
    }

    float inv0 = 1.f / l0, inv1 = 1.f / l1;
    int row0 = qb * 64 + w * 16 + lq;
    float* o0 = O + ((size_t)(b * SS + row0) * HH + h) * DK;
    float* o1 = o0 + (size_t)8 * HH * DK;
    #pragma unroll
    for (int dn = 0; dn < 8; dn++) {
        int d = dn * 8 + 2 * lr;
        *(float2*)(o0 + d) = make_float2(acc[dn][0] * inv0, acc[dn][1] * inv0);
        *(float2*)(o1 + d) = make_float2(acc[dn][2] * inv1, acc[dn][3] * inv1);
    }
}

// ============ 3xBF16 split GEMM, ldmatrix frags, BKT=32 ====================
// C[M,N] = A[M,K] @ op(B) (+bias)(+residual), fp32 in/out.
//   NT=false : B is [K,N] row-major;  NT=true : B is [N,K] row-major (B^T).
// Tiles: 128x128x32; 256 threads, 8 warps (2x4), warp tile 64x32.
// Smem: A and B both stored [row][32 bf16] with 80-byte row stride (hi & lo),
// double-buffered; fragments via ldmatrix.x4 (conflict-free: r*20 mod 32 walk).
#define G_BM 128
#define G_BN 128
#define G_BK 32
#define G_RS 80                     // row stride bytes (64 data + 16 pad)
#define G_TILE (128 * G_RS)         // 10240 bytes, one [128][32] bf16 tile
#define G_ASH 0
#define G_ASL (2 * G_TILE)
#define G_BSH (4 * G_TILE)
#define G_BSL (6 * G_TILE)
#define G_SMEM (8 * G_TILE)         // 81920 bytes

__device__ __forceinline__ unsigned smem_u32(const void* p) {
    unsigned r;
    asm("{ .reg .u64 t; cvta.to.shared.u64 t, %1; cvt.u32.u64 %0, t; }" : "=r"(r) : "l"(p));
    return r;
}

template<bool NT>
__global__ __launch_bounds__(256)
void gemm_tc_kernel(const float* __restrict__ A, const float* __restrict__ B,
                    const float* __restrict__ bias, const float* __restrict__ res,
                    float* __restrict__ C, int Nd, int Kd) {
    extern __shared__ char smem[];
    const unsigned sbase = smem_u32(smem);

    const int t    = threadIdx.x;
    const int lane = t & 31;
    const int warp = t >> 5;
    const int wm   = warp >> 2;          // 0..1
    const int wn   = warp & 3;           // 0..3
    const int bm   = blockIdx.y * G_BM;
    const int bn   = blockIdx.x * G_BN;

    // A staging: row ar, k-half kh (16 k each)
    const int ar = t >> 1;
    const int kh = t & 1;
    // B staging: n-row nn, k-half bh
    const int nn = t & 127;
    const int bh = t >> 7;
    const bool bok = NT || (bn + nn < Nd);

    float4 aR[4];
    float4 bR4[4];      // NT path
    float  bR[16];      // NN path
    float  acc[4][4][4] = {};

    const int nkt = Kd / G_BK;

    auto g_load = [&](int kt) {
        const int k0 = kt * G_BK;
        const float* ap = A + (size_t)(bm + ar) * Kd + k0 + kh * 16;
        #pragma unroll
        for (int j = 0; j < 4; j++) aR[j] = *(const float4*)(ap + j * 4);
        if (NT) {
            const float* bp = B + (size_t)(bn + nn) * Kd + k0 + bh * 16;
            #pragma unroll
            for (int j = 0; j < 4; j++) bR4[j] = *(const float4*)(bp + j * 4);
        } else {
            #pragma unroll
            for (int i = 0; i < 16; i++)
                bR[i] = bok ? B[(size_t)(k0 + bh * 16 + i) * Nd + bn + nn] : 0.f;
        }
    };
    auto s_store = [&](int buf) {
        const unsigned bufo = buf * G_TILE;
        // A rows
        {
            unsigned addr = sbase + G_ASH + bufo + ar * G_RS + kh * 32;
            unsigned addl = sbase + G_ASL + bufo + ar * G_RS + kh * 32;
            #pragma unroll
            for (int j = 0; j < 4; j++) {
                unsigned h0, l0, h1, l1;
                split2(aR[j].x, aR[j].y, h0, l0);
                split2(aR[j].z, aR[j].w, h1, l1);
                asm volatile("st.shared.v2.b32 [%0], {%1,%2};" :: "r"(addr + j * 8), "r"(h0), "r"(h1) : "memory");
                asm volatile("st.shared.v2.b32 [%0], {%1,%2};" :: "r"(addl + j * 8), "r"(l0), "r"(l1) : "memory");
            }
        }
        // B rows ([n][k] layout)
        {
            unsigned addr = sbase + G_BSH + bufo + nn * G_RS + bh * 32;
            unsigned addl = sbase + G_BSL + bufo + nn * G_RS + bh * 32;
            #pragma unroll
            for (int j = 0; j < 4; j++) {
                unsigned h0, l0, h1, l1;
                if (NT) {
                    split2(bR4[j].x, bR4[j].y, h0, l0);
                    split2(bR4[j].z, bR4[j].w, h1, l1);
                } else {
                    split2(bR[4*j],   bR[4*j+1], h0, l0);
                    split2(bR[4*j+2], bR[4*j+3], h1, l1);
                }
                asm volatile("st.shared.v2.b32 [%0], {%1,%2};" :: "r"(addr + j * 8), "r"(h0), "r"(h1) : "memory");
                asm volatile("st.shared.v2.b32 [%0], {%1,%2};" :: "r"(addl + j * 8), "r"(l0), "r"(l1) : "memory");
            }
        }
    };

    g_load(0);
    s_store(0);
    __syncthreads();

    const int m0 = wm * 64;
    const int n0 = wn * 32;
    const int lq = lane >> 2;
    const int lr = lane & 3;
    // ldmatrix lane->address components
    const unsigned aRowOff = (unsigned)(lane & 15) * G_RS + (unsigned)(lane >> 4) * 16;
    const unsigned bRowOff = ((unsigned)((lane >> 4) * 8 + (lane & 7))) * G_RS
                           + (unsigned)((lane >> 3) & 1) * 16;

    for (int kt = 0; kt < nkt; kt++) {
        const int cur = kt & 1;
        const unsigned bufo = cur * G_TILE;
        if (kt + 1 < nkt) g_load(kt + 1);

        #pragma unroll
        for (int ks = 0; ks < 2; ks++) {
            unsigned aH[4][4], aL[4][4], bH[2][4], bL[2][4];
            const unsigned ksb = ks * 32;
            #pragma unroll
            for (int mi = 0; mi < 4; mi++) {
                unsigned ah = sbase + G_ASH + bufo + (m0 + mi * 16) * G_RS + ksb + aRowOff;
                unsigned al = sbase + G_ASL + bufo + (m0 + mi * 16) * G_RS + ksb + aRowOff;
                LDSM4(aH[mi][0], aH[mi][1], aH[mi][2], aH[mi][3], ah);
                LDSM4(aL[mi][0], aL[mi][1], aL[mi][2], aL[mi][3], al);
            }
            #pragma unroll
            for (int ng = 0; ng < 2; ng++) {
                unsigned bhh = sbase + G_BSH + bufo + (n0 + ng * 16) * G_RS + ksb + bRowOff;
                unsigned bll = sbase + G_BSL + bufo + (n0 + ng * 16) * G_RS + ksb + bRowOff;
                LDSM4(bH[ng][0], bH[ng][1], bH[ng][2], bH[ng][3], bhh);
                LDSM4(bL[ng][0], bL[ng][1], bL[ng][2], bL[ng][3], bll);
            }
            #pragma unroll
            for (int mi = 0; mi < 4; mi++)
                #pragma unroll
                for (int ng = 0; ng < 2; ng++) {
                    float* acc0 = acc[mi][ng * 2];
                    float* acc1 = acc[mi][ng * 2 + 1];
                    BF16MMA(acc0, aH[mi], (bH[ng] + 0));
                    BF16MMA(acc0, aL[mi], (bH[ng] + 0));
                    BF16MMA(acc0, aH[mi], (bL[ng] + 0));
                    BF16MMA(acc1, aH[mi], (bH[ng] + 2));
                    BF16MMA(acc1, aL[mi], (bH[ng] + 2));
                    BF16MMA(acc1, aH[mi], (bL[ng] + 2));
                }
        }

        if (kt + 1 < nkt) s_store((kt + 1) & 1);
        __syncthreads();
    }

    // ---- epilogue
    #pragma unroll
    for (int mi = 0; mi < 4; mi++) {
        int row = bm + m0 + mi * 16 + lq;
        #pragma unroll
        for (int ni = 0; ni < 4; ni++) {
            int col = bn + n0 + ni * 8 + lr * 2;
            if (col < Nd) {
                float v0 = acc[mi][ni][0], v1 = acc[mi][ni][1];
                float v2 = acc[mi][ni][2], v3 = acc[mi][ni][3];
                if (bias) {
                    float bx = bias[col], by = bias[col + 1];
                    v0 += bx; v1 += by; v2 += bx; v3 += by;
                }
                size_t o0 = (size_t)row * Nd + col;
                size_t o1 = (size_t)(row + 8) * Nd + col;
                if (res) {
                    v0 += res[o0]; v1 += res[o0 + 1];
                    v2 += res[o1]; v3 += res[o1 + 1];
                }
                C[o0] = v0; C[o0 + 1] = v1;
                C[o1] = v2; C[o1 + 1] = v3;
            }
        }
    }
}

// ---------------- silu(f1)*f2 -> f1 ----------------
__global__ void silumul_kernel(float* __restrict__ f1, const float* __restrict__ f2, int n) {
    int i = blockIdx.x * blockDim.x + threadIdx.x;
    if (i < n) {
        float a = f1[i];
        float s = a / (1.0f + __expf(-a));
        f1[i] = s * f2[i];
    }
}

// ---------------- host driver ----------------
extern "C" void kernel_launch(void* const* d_in, const int* in_sizes, int n_in,
                              void* d_out, int out_size) {
    const int*   tokens = (const int*)  d_in[0];
    const float* emb    = (const float*)d_in[1];
    const float* wq = (const float*)d_in[2];
    const float* bq = (const float*)d_in[3];
    const float* wk = (const float*)d_in[4];
    const float* bk = (const float*)d_in[5];
    const float* wv = (const float*)d_in[6];
    const float* bv = (const float*)d_in[7];
    const float* wo = (const float*)d_in[8];
    const float* bo = (const float*)d_in[9];
    const float* w1 = (const float*)d_in[10];
    const float* b1 = (const float*)d_in[11];
    const float* w2 = (const float*)d_in[12];
    const float* b2 = (const float*)d_in[13];
    const float* w3 = (const float*)d_in[14];
    const float* b3 = (const float*)d_in[15];
    const float* g1 = (const float*)d_in[16];
    const float* g2 = (const float*)d_in[17];
    const float* gpost = (const float*)d_in[18];
    const float* fcos  = (const float*)d_in[19];
    const float* fsin  = (const float*)d_in[20];
    float* out = (float*)d_out;

    float *x, *h, *q, *k, *v, *o, *f1, *f2;
    cudaGetSymbolAddress((void**)&x,  g_x);
    cudaGetSymbolAddress((void**)&h,  g_h);
    cudaGetSymbolAddress((void**)&q,  g_q);
    cudaGetSymbolAddress((void**)&k,  g_k);
    cudaGetSymbolAddress((void**)&v,  g_v);
    cudaGetSymbolAddress((void**)&o,  g_o);
    cudaGetSymbolAddress((void**)&f1, g_f1);
    cudaGetSymbolAddress((void**)&f2, g_f2);

    cudaFuncSetAttribute(gemm_tc_kernel<false>,
                         cudaFuncAttributeMaxDynamicSharedMemorySize, G_SMEM);
    cudaFuncSetAttribute(gemm_tc_kernel<true>,
                         cudaFuncAttributeMaxDynamicSharedMemorySize, G_SMEM);

    embed_kernel<<<MM, 256>>>(tokens, emb, x);

    const int KVN = KVH * DK;   // 512
    const int GY  = MM / G_BM;  // 32
    for (int l = 0; l < NL; l++) {
        rmsnorm_kernel<<<MM, 256>>>(x, g1 + (size_t)l * DD, h);

        gemm_tc_kernel<false><<<dim3(DD / G_BN, GY), 256, G_SMEM>>>(
            h, wq + (size_t)l * DD * DD, bq + (size_t)l * DD, nullptr, q, DD, DD);
        gemm_tc_kernel<false><<<dim3(KVN / G_BN, GY), 256, G_SMEM>>>(
            h, wk + (size_t)l * DD * KVN, bk + (size_t)l * KVN, nullptr, k, KVN, DD);
        gemm_tc_kernel<false><<<dim3(KVN / G_BN, GY), 256, G_SMEM>>>(
            h, wv + (size_t)l * DD * KVN, bv + (size_t)l * KVN, nullptr, v, KVN, DD);

        int tq = MM * HH * 32,  tk = MM * KVH * 32;
        rope_kernel<<<(tq + 255) / 256, 256>>>(q, fcos, fsin, HH, tq);
        rope_kernel<<<(tk + 255) / 256, 256>>>(k, fcos, fsin, KVH, tk);

        attn_tc_kernel<<<dim3(SS / 64, HH, BB), 128>>>(q, k, v, o);

        gemm_tc_kernel<false><<<dim3(DD / G_BN, GY), 256, G_SMEM>>>(
            o, wo + (size_t)l * DD * DD, bo + (size_t)l * DD, x, x, DD, DD);

        rmsnorm_kernel<<<MM, 256>>>(x, g2 + (size_t)l * DD, h);

        int gnx = (FD + G_BN - 1) / G_BN;   // 22
        gemm_tc_kernel<false><<<dim3(gnx, GY), 256, G_SMEM>>>(
            h, w1 + (size_t)l * DD * FD, b1 + (size_t)l * FD, nullptr, f1, FD, DD);
        gemm_tc_kernel<false><<<dim3(gnx, GY), 256, G_SMEM>>>(
            h, w2 + (size_t)l * DD * FD, b2 + (size_t)l * FD, nullptr, f2, FD, DD);

        int nsm = MM * FD;
        silumul_kernel<<<(nsm + 255) / 256, 256>>>(f1, f2, nsm);

        gemm_tc_kernel<false><<<dim3(DD / G_BN, GY), 256, G_SMEM>>>(
            f1, w3 + (size_t)l * FD * DD, b3 + (size_t)l * DD, x, x, DD, FD);
    }

    rmsnorm_kernel<<<MM, 256>>>(x, gpost, h);
    gemm_tc_kernel<true><<<dim3(VV / G_BN, GY), 256, G_SMEM>>>(
        h, emb, nullptr, nullptr, out, VV, DD);
}

// round 8
// speedup vs baseline: 1.9069x; 1.0907x over previous
#include <cuda_runtime.h>
#include <cuda_bf16.h>
#include <math.h>
#include <stdint.h>

// Problem dims (fixed by the dataset)
#define BB   2
#define SS   2048
#define DD   1024
#define HH   16
#define KVH  8
#define DK   64
#define FD   2752
#define NL   4
#define VV   32000
#define MM   (BB*SS)          // 4096 token rows
#define KVN  (KVH*DK)         // 512

// ---------------- scratch (device globals: no allocations allowed) ----------
__device__ float g_x [MM*DD];
__device__ float g_q [MM*DD];
__device__ float g_k [MM*KVN];
__device__ float g_v [MM*KVN];
__device__ float g_f1[(size_t)MM*FD];
__device__ float g_f2[(size_t)MM*FD];

// split activations
__device__ __nv_bfloat16 g_hH [MM*DD],  g_hL [MM*DD];
__device__ __nv_bfloat16 g_oH [MM*DD],  g_oL [MM*DD];
__device__ __nv_bfloat16 g_f1H[(size_t)MM*FD], g_f1L[(size_t)MM*FD];

// split transposed weights ([N][K] layout)
__device__ __nv_bfloat16 g_wqH[(size_t)NL*DD*DD],  g_wqL[(size_t)NL*DD*DD];
__device__ __nv_bfloat16 g_wkH[(size_t)NL*DD*KVN], g_wkL[(size_t)NL*DD*KVN];
__device__ __nv_bfloat16 g_wvH[(size_t)NL*DD*KVN], g_wvL[(size_t)NL*DD*KVN];
__device__ __nv_bfloat16 g_woH[(size_t)NL*DD*DD],  g_woL[(size_t)NL*DD*DD];
__device__ __nv_bfloat16 g_w1H[(size_t)NL*DD*FD],  g_w1L[(size_t)NL*DD*FD];
__device__ __nv_bfloat16 g_w2H[(size_t)NL*DD*FD],  g_w2L[(size_t)NL*DD*FD];
__device__ __nv_bfloat16 g_w3H[(size_t)NL*FD*DD],  g_w3L[(size_t)NL*FD*DD];
__device__ __nv_bfloat16 g_ebH[(size_t)VV*DD],     g_ebL[(size_t)VV*DD];

// ---------------- bf16 split helper ----------------
__device__ __forceinline__ void split2(float x0, float x1,
                                       unsigned &hi, unsigned &lo) {
    __nv_bfloat162 h = __floats2bfloat162_rn(x0, x1);
    float h0 = __bfloat162float(h.x);
    float h1 = __bfloat162float(h.y);
    __nv_bfloat162 l = __floats2bfloat162_rn(x0 - h0, x1 - h1);
    hi = *reinterpret_cast<unsigned*>(&h);
    lo = *reinterpret_cast<unsigned*>(&l);
}

// ---------------- embedding gather ----------------
__global__ void embed_kernel(const int* __restrict__ tokens,
                             const float* __restrict__ emb,
                             float* __restrict__ x) {
    int row = blockIdx.x;
    int tok = tokens[row];
    const float4* src = (const float4*)(emb + (size_t)tok * DD);
    float4*       dst = (float4*)(x + (size_t)row * DD);
    dst[threadIdx.x] = src[threadIdx.x];
}

// ---------------- elementwise split (embed table) ----------------
__global__ void esplit_kernel(const float* __restrict__ W,
                              __nv_bfloat16* __restrict__ H,
                              __nv_bfloat16* __restrict__ L) {
    size_t i = ((size_t)blockIdx.x * 256 + threadIdx.x) * 4;
    float4 v = *(const float4*)(W + i);
    unsigned h0, l0, h1, l1;
    split2(v.x, v.y, h0, l0);
    split2(v.z, v.w, h1, l1);
    *(uint2*)(H + i) = make_uint2(h0, h1);
    *(uint2*)(L + i) = make_uint2(l0, l1);
}

// ---------------- transpose + split: W[K][N] -> H/L[N][K] ----------------
__global__ void tsplit_kernel(const float* __restrict__ W,
                              __nv_bfloat16* __restrict__ H,
                              __nv_bfloat16* __restrict__ L, int K, int N) {
    __shared__ float tile[32][33];
    int n0 = blockIdx.x * 32, k0 = blockIdx.y * 32;
    int tx = threadIdx.x, ty = threadIdx.y;
    #pragma unroll
    for (int i = 0; i < 32; i += 8)
        tile[ty + i][tx] = W[(size_t)(k0 + ty + i) * N + n0 + tx];
    __syncthreads();
    #pragma unroll
    for (int i = 0; i < 32; i += 8) {
        int n = n0 + ty + i, k = k0 + tx;
        float v = tile[tx][ty + i];
        __nv_bfloat16 h = __float2bfloat16_rn(v);
        H[(size_t)n * K + k] = h;
        L[(size_t)n * K + k] = __float2bfloat16_rn(v - __bfloat162float(h));
    }
}

// ---------------- rmsnorm -> split output ----------------
__global__ void rmsnorm_split_kernel(const float* __restrict__ x,
                                     const float* __restrict__ g,
                                     __nv_bfloat16* __restrict__ H,
                                     __nv_bfloat16* __restrict__ L) {
    int row = blockIdx.x;
    const float4* xr = (const float4*)(x + (size_t)row * DD);
    float4 v = xr[threadIdx.x];
    float ss = v.x*v.x + v.y*v.y + v.z*v.z + v.w*v.w;
    #pragma unroll
    for (int o = 16; o; o >>= 1) ss += __shfl_xor_sync(0xffffffffu, ss, o);
    __shared__ float red[8];
    if ((threadIdx.x & 31) == 0) red[threadIdx.x >> 5] = ss;
    __syncthreads();
    if (threadIdx.x < 8) {
        float r = red[threadIdx.x];
        #pragma unroll
        for (int o = 4; o; o >>= 1) r += __shfl_xor_sync(0xffu, r, o);
        if (threadIdx.x == 0) red[0] = r;
    }
    __syncthreads();
    float inv = rsqrtf(red[0] * (1.0f / DD) + 1e-6f);
    const float4* g4 = (const float4*)g;
    float4 gg = g4[threadIdx.x];
    float o0 = v.x*inv*gg.x, o1 = v.y*inv*gg.y, o2 = v.z*inv*gg.z, o3 = v.w*inv*gg.w;
    unsigned h0, l0, h1, l1;
    split2(o0, o1, h0, l0);
    split2(o2, o3, h1, l1);
    size_t base = (size_t)row * DD + threadIdx.x * 4;
    *(uint2*)(H + base) = make_uint2(h0, h1);
    *(uint2*)(L + base) = make_uint2(l0, l1);
}

// ---------------- rope (interleaved pairs) ----------------
__global__ void rope_kernel(float* __restrict__ buf,
                            const float* __restrict__ cosb,
                            const float* __restrict__ sinb,
                            int nheads, int total) {
    int idx = blockIdx.x * blockDim.x + threadIdx.x;
    if (idx >= total) return;
    int p    = idx & 31;
    int hrow = idx >> 5;
    int row  = hrow / nheads;
    int s    = row & (SS - 1);
    float c  = cosb[s * 32 + p];
    float sn = sinb[s * 32 + p];
    float* base = buf + (size_t)hrow * DK + p * 2;
    float xr = base[0], xi = base[1];
    base[0] = xr * c - xi * sn;
    base[1] = xr * sn + xi * c;
}

#define BF16MMA(D, Ar, Br)                                                    \
    asm volatile(                                                             \
        "mma.sync.aligned.m16n8k16.row.col.f32.bf16.bf16.f32 "                \
        "{%0,%1,%2,%3}, {%4,%5,%6,%7}, {%8,%9}, {%0,%1,%2,%3};"               \
        : "+f"(D[0]), "+f"(D[1]), "+f"(D[2]), "+f"(D[3])                      \
        : "r"(Ar[0]), "r"(Ar[1]), "r"(Ar[2]), "r"(Ar[3]),                     \
          "r"(Br[0]), "r"(Br[1]))

#define LDSM4(R0, R1, R2, R3, ADDR)                                           \
    asm volatile("ldmatrix.sync.aligned.m8n8.x4.shared.b16 {%0,%1,%2,%3}, [%4];" \
        : "=r"(R0), "=r"(R1), "=r"(R2), "=r"(R3) : "r"(ADDR))

// ======== flash attention v2, tensor-core, 3xBF16 split, causal, GQA =======
#define KSTR 72
__global__ __launch_bounds__(128)
void attn_tc_kernel(const float* __restrict__ Q, const float* __restrict__ K,
                    const float* __restrict__ V,
                    __nv_bfloat16* __restrict__ OH, __nv_bfloat16* __restrict__ OL) {
    __shared__ unsigned KsH[32][KSTR], KsL[32][KSTR];
    __shared__ unsigned VsH[32][KSTR], VsL[32][KSTR];

    const int qb   = gridDim.x - 1 - blockIdx.x;
    const int hd   = blockIdx.y;
    const int b    = blockIdx.z;
    const int kh   = hd >> 1;
    const int t    = threadIdx.x;
    const int lane = t & 31;
    const int w    = t >> 5;
    const int lq   = lane >> 2;
    const int lr   = lane & 3;

    unsigned qaH[4][4], qaL[4][4];
    {
        const int r0 = qb * 64 + w * 16 + lq;
        const float* q0p = Q + ((size_t)(b * SS + r0) * HH + hd) * DK;
        const float* q1p = q0p + (size_t)8 * HH * DK;
        #pragma unroll
        for (int kb = 0; kb < 4; kb++) {
            float2 v0 = *(const float2*)(q0p + kb * 16 + 2 * lr);
            float2 v1 = *(const float2*)(q1p + kb * 16 + 2 * lr);
            float2 v2 = *(const float2*)(q0p + kb * 16 + 8 + 2 * lr);
            float2 v3 = *(const float2*)(q1p + kb * 16 + 8 + 2 * lr);
            split2(v0.x * 0.125f, v0.y * 0.125f, qaH[kb][0], qaL[kb][0]);
            split2(v1.x * 0.125f, v1.y * 0.125f, qaH[kb][1], qaL[kb][1]);
            split2(v2.x * 0.125f, v2.y * 0.125f, qaH[kb][2], qaL[kb][2]);
            split2(v3.x * 0.125f, v3.y * 0.125f, qaH[kb][3], qaL[kb][3]);
        }
    }

    float acc[8][4] = {};
    float m0 = -1e30f, m1 = -1e30f, l0 = 0.f, l1 = 0.f;

    const int ntiles = qb + 1;
    for (int kt = 0; kt < ntiles; kt++) {
        const int kbase = kt * 64;
        if (kt) __syncthreads();
        {
            int krow = t >> 1, hf = t & 1;
            const float* kp_ = K + ((size_t)(b * SS + kbase + krow) * KVH + kh) * DK + hf * 32;
            #pragma unroll
            for (int i = 0; i < 8; i++) {
                float4 kv = ((const float4*)kp_)[i];
                int dp = hf * 16 + i * 2;
                split2(kv.x, kv.y, KsH[dp][krow],     KsL[dp][krow]);
                split2(kv.z, kv.w, KsH[dp + 1][krow], KsL[dp + 1][krow]);
            }
        }
        {
            int kp2 = t >> 2, q4 = t & 3;
            const float* vr0 = V + ((size_t)(b * SS + kbase + 2 * kp2) * KVH + kh) * DK + q4 * 16;
            const float* vr1 = vr0 + (size_t)KVH * DK;
            #pragma unroll
            for (int i = 0; i < 4; i++) {
                float4 a = ((const float4*)vr0)[i];
                float4 c = ((const float4*)vr1)[i];
                int d = q4 * 16 + i * 4;
                split2(a.x, c.x, VsH[kp2][d],     VsL[kp2][d]);
                split2(a.y, c.y, VsH[kp2][d + 1], VsL[kp2][d + 1]);
                split2(a.z, c.z, VsH[kp2][d + 2], VsL[kp2][d + 2]);
                split2(a.w, c.w, VsH[kp2][d + 3], VsL[kp2][d + 3]);
            }
        }
        __syncthreads();

        float s[8][4] = {};
        #pragma unroll
        for (int kb = 0; kb < 4; kb++) {
            unsigned kfH[8][2], kfL[8][2];
            #pragma unroll
            for (int ni = 0; ni < 8; ni++) {
                kfH[ni][0] = KsH[kb * 8 + lr][ni * 8 + lq];
                kfH[ni][1] = KsH[kb * 8 + lr + 4][ni * 8 + lq];
                kfL[ni][0] = KsL[kb * 8 + lr][ni * 8 + lq];
                kfL[ni][1] = KsL[kb * 8 + lr + 4][ni * 8 + lq];
            }
            #pragma unroll
            for (int ni = 0; ni < 8; ni++) {
                BF16MMA(s[ni], qaH[kb], kfH[ni]);
                BF16MMA(s[ni], qaL[kb], kfH[ni]);
                BF16MMA(s[ni], qaH[kb], kfL[ni]);
            }
        }

        if (kt == qb) {
            int row0 = qb * 64 + w * 16 + lq;
            #pragma unroll
            for (int ni = 0; ni < 8; ni++) {
                int col = kbase + ni * 8 + 2 * lr;
                if (col     > row0)     s[ni][0] = -1e30f;
                if (col + 1 > row0)     s[ni][1] = -1e30f;
                if (col     > row0 + 8) s[ni][2] = -1e30f;
                if (col + 1 > row0 + 8) s[ni][3] = -1e30f;
            }
        }

        float mt0 = -1e30f, mt1 = -1e30f;
        #pragma unroll
        for (int ni = 0; ni < 8; ni++) {
            mt0 = fmaxf(mt0, fmaxf(s[ni][0], s[ni][1]));
            mt1 = fmaxf(mt1, fmaxf(s[ni][2], s[ni][3]));
        }
        mt0 = fmaxf(mt0, __shfl_xor_sync(0xffffffffu, mt0, 1));
        mt0 = fmaxf(mt0, __shfl_xor_sync(0xffffffffu, mt0, 2));
        mt1 = fmaxf(mt1, __shfl_xor_sync(0xffffffffu, mt1, 1));
        mt1 = fmaxf(mt1, __shfl_xor_sync(0xffffffffu, mt1, 2));
        float mn0 = fmaxf(m0, mt0), mn1 = fmaxf(m1, mt1);
        float c0 = __expf(m0 - mn0), c1 = __expf(m1 - mn1);
        m0 = mn0; m1 = mn1;
        float rs0 = 0.f, rs1 = 0.f;
        #pragma unroll
        for (int ni = 0; ni < 8; ni++) {
            s[ni][0] = __expf(s[ni][0] - mn0);
            s[ni][1] = __expf(s[ni][1] - mn0);
            s[ni][2] = __expf(s[ni][2] - mn1);
            s[ni][3] = __expf(s[ni][3] - mn1);
            rs0 += s[ni][0] + s[ni][1];
            rs1 += s[ni][2] + s[ni][3];
        }
        rs0 += __shfl_xor_sync(0xffffffffu, rs0, 1);
        rs0 += __shfl_xor_sync(0xffffffffu, rs0, 2);
        rs1 += __shfl_xor_sync(0xffffffffu, rs1, 1);
        rs1 += __shfl_xor_sync(0xffffffffu, rs1, 2);
        l0 = l0 * c0 + rs0;
        l1 = l1 * c1 + rs1;
        #pragma unroll
        for (int dn = 0; dn < 8; dn++) {
            acc[dn][0] *= c0; acc[dn][1] *= c0;
            acc[dn][2] *= c1; acc[dn][3] *= c1;
        }

        #pragma unroll
        for (int kb = 0; kb < 4; kb++) {
            unsigned aPH[4], aPL[4];
            split2(s[2*kb][0],   s[2*kb][1],   aPH[0], aPL[0]);
            split2(s[2*kb][2],   s[2*kb][3],   aPH[1], aPL[1]);
            split2(s[2*kb+1][0], s[2*kb+1][1], aPH[2], aPL[2]);
            split2(s[2*kb+1][2], s[2*kb+1][3], aPH[3], aPL[3]);
            #pragma unroll
            for (int dn = 0; dn < 8; dn++) {
                unsigned vfH[2], vfL[2];
                vfH[0] = VsH[kb * 8 + lr][dn * 8 + lq];
                vfH[1] = VsH[kb * 8 + lr + 4][dn * 8 + lq];
                vfL[0] = VsL[kb * 8 + lr][dn * 8 + lq];
                vfL[1] = VsL[kb * 8 + lr + 4][dn * 8 + lq];
                BF16MMA(acc[dn], aPH, vfH);
                BF16MMA(acc[dn], aPL, vfH);
                BF16MMA(acc[dn], aPH, vfL);
            }
        }
    }

    float inv0 = 1.f / l0, inv1 = 1.f / l1;
    int row0 = qb * 64 + w * 16 + lq;
    size_t b0 = ((size_t)(b * SS + row0) * HH + hd) * DK;
    size_t b1 = b0 + (size_t)8 * HH * DK;
    #pragma unroll
    for (int dn = 0; dn < 8; dn++) {
        int d = dn * 8 + 2 * lr;
        unsigned h_, l_;
        split2(acc[dn][0] * inv0, acc[dn][1] * inv0, h_, l_);
        *(unsigned*)(OH + b0 + d) = h_;
        *(unsigned*)(OL + b0 + d) = l_;
        split2(acc[dn][2] * inv1, acc[dn][3] * inv1, h_, l_);
        *(unsigned*)(OH + b1 + d) = h_;
        *(unsigned*)(OL + b1 + d) = l_;
    }
}

// ========== pure-bf16 split GEMM, cp.async 3-stage, ldmatrix ===============
// C[M,N] = (AH+AL)[M][K] @ (BH+BL)[N][K]^T (+bias)(+residual), fp32 out.
// Tiles 128x128x32; 256 threads, 8 warps (2x4), warp tile 64x32.
#define G_BK 32
#define G_RS 80                     // smem row stride bytes (64 data + 16 pad)
#define G_TILE (128 * G_RS)         // 10240
#define STAGE_B (4 * G_TILE)        // AH, AL, BH, BL per stage
#define G_SMEM (3 * STAGE_B)        // 122880

__device__ __forceinline__ unsigned smem_u32(const void* p) {
    unsigned r;
    asm("{ .reg .u64 t; cvta.to.shared.u64 t, %1; cvt.u32.u64 %0, t; }" : "=r"(r) : "l"(p));
    return r;
}

__global__ __launch_bounds__(256)
void gemm_bb_kernel(const __nv_bfloat16* __restrict__ AH_, const __nv_bfloat16* __restrict__ AL_,
                    const __nv_bfloat16* __restrict__ BH_, const __nv_bfloat16* __restrict__ BL_,
                    const float* __restrict__ bias, const float* __restrict__ res,
                    float* __restrict__ C, int Nd, int Kd) {
    extern __shared__ char smem[];
    const unsigned sbase = smem_u32(smem);
    const int t    = threadIdx.x;
    const int lane = t & 31;
    const int warp = t >> 5;
    const int wm   = warp >> 2;
    const int wn   = warp & 3;
    const int bm   = blockIdx.y * 128;
    const int bn   = blockIdx.x * 128;

    // staging assignment: 64 threads per tile (AH/AL/BH/BL)
    const int tile = t >> 6;
    const int tt   = t & 63;
    const int quad = tt & 3;
    const int r0s  = tt >> 2;
    const __nv_bfloat16* sbptr = (tile == 0) ? AH_ : (tile == 1) ? AL_
                               : (tile == 2) ? BH_ : BL_;
    const int rbase = (tile >= 2) ? bn : bm;
    const bool isB  = (tile >= 2);

    float acc[4][4][4] = {};
    const int nkt = Kd / G_BK;

    auto issue_stage = [&](int kt) {
        const int k0 = kt * G_BK;
        unsigned sb = sbase + (kt % 3) * STAGE_B + tile * G_TILE;
        #pragma unroll
        for (int j = 0; j < 8; j++) {
            int row = r0s + 16 * j;
            const __nv_bfloat16* src = sbptr + (size_t)(rbase + row) * Kd + k0 + quad * 8;
            unsigned dst = sb + row * G_RS + quad * 16;
            int vsz = (!isB || (bn + row) < Nd) ? 16 : 0;
            asm volatile("cp.async.cg.shared.global [%0], [%1], 16, %2;"
                         :: "r"(dst), "l"(src), "r"(vsz) : "memory");
        }
        asm volatile("cp.async.commit_group;" ::: "memory");
    };

    issue_stage(0);
    issue_stage(1);

    const int m0 = wm * 64;
    const int n0 = wn * 32;
    const int lq = lane >> 2;
    const int lr = lane & 3;
    const unsigned aRowOff = (unsigned)(lane & 15) * G_RS + (unsigned)(lane >> 4) * 16;
    const unsigned bRowOff = ((unsigned)((lane >> 4) * 8 + (lane & 7))) * G_RS
                           + (unsigned)((lane >> 3) & 1) * 16;

    for (int kt = 0; kt < nkt; kt++) {
        asm volatile("cp.async.wait_group 1;" ::: "memory");
        __syncthreads();
        if (kt + 2 < nkt) issue_stage(kt + 2);
        else asm volatile("cp.async.commit_group;" ::: "memory");

        const unsigned stb = sbase + (kt % 3) * STAGE_B;
        #pragma unroll
        for (int ks = 0; ks < 2; ks++) {
            unsigned aH[4][4], aL[4][4], bH[2][4], bL[2][4];
            const unsigned ksb = ks * 32;
            #pragma unroll
            for (int mi = 0; mi < 4; mi++) {
                unsigned ah = stb + (m0 + mi * 16) * G_RS + ksb + aRowOff;
                unsigned al = ah + G_TILE;
                LDSM4(aH[mi][0], aH[mi][1], aH[mi][2], aH[mi][3], ah);
                LDSM4(aL[mi][0], aL[mi][1], aL[mi][2], aL[mi][3], al);
            }
            #pragma unroll
            for (int ng = 0; ng < 2; ng++) {
                unsigned bhh = stb + 2 * G_TILE + (n0 + ng * 16) * G_RS + ksb + bRowOff;
                unsigned bll = bhh + G_TILE;
                LDSM4(bH[ng][0], bH[ng][1], bH[ng][2], bH[ng][3], bhh);
                LDSM4(bL[ng][0], bL[ng][1], bL[ng][2], bL[ng][3], bll);
            }
            #pragma unroll
            for (int mi = 0; mi < 4; mi++)
                #pragma unroll
                for (int ng = 0; ng < 2; ng++) {
                    float* acc0 = acc[mi][ng * 2];
                    float* acc1 = acc[mi][ng * 2 + 1];
                    BF16MMA(acc0, aH[mi], (bH[ng] + 0));
                    BF16MMA(acc0, aL[mi], (bH[ng] + 0));
                    BF16MMA(acc0, aH[mi], (bL[ng] + 0));
                    BF16MMA(acc1, aH[mi], (bH[ng] + 2));
                    BF16MMA(acc1, aL[mi], (bH[ng] + 2));
                    BF16MMA(acc1, aH[mi], (bL[ng] + 2));
                }
        }
    }

    // ---- epilogue
    #pragma unroll
    for (int mi = 0; mi < 4; mi++) {
        int row = bm + m0 + mi * 16 + lq;
        #pragma unroll
        for (int ni = 0; ni < 4; ni++) {
            int col = bn + n0 + ni * 8 + lr * 2;
            if (col < Nd) {
                float v0 = acc[mi][ni][0], v1 = acc[mi][ni][1];
                float v2 = acc[mi][ni][2], v3 = acc[mi][ni][3];
                if (bias) {
                    float bx = bias[col], by = bias[col + 1];
                    v0 += bx; v1 += by; v2 += bx; v3 += by;
                }
                size_t o0 = (size_t)row * Nd + col;
                size_t o1 = (size_t)(row + 8) * Nd + col;
                if (res) {
                    v0 += res[o0]; v1 += res[o0 + 1];
                    v2 += res[o1]; v3 += res[o1 + 1];
                }
                C[o0] = v0; C[o0 + 1] = v1;
                C[o1] = v2; C[o1 + 1] = v3;
            }
        }
    }
}

// ---------------- silu(f1)*f2 -> split ----------------
__global__ void silumul_split_kernel(const float* __restrict__ f1,
                                     const float* __restrict__ f2,
                                     __nv_bfloat16* __restrict__ H,
                                     __nv_bfloat16* __restrict__ L) {
    size_t i = (size_t)blockIdx.x * 256 + threadIdx.x;   // pair index
    float2 a = ((const float2*)f1)[i];
    float2 b = ((const float2*)f2)[i];
    float g0 = a.x / (1.0f + __expf(-a.x)) * b.x;
    float g1 = a.y / (1.0f + __expf(-a.y)) * b.y;
    unsigned h_, l_;
    split2(g0, g1, h_, l_);
    ((unsigned*)H)[i] = h_;
    ((unsigned*)L)[i] = l_;
}

// ---------------- host driver ----------------
extern "C" void kernel_launch(void* const* d_in, const int* in_sizes, int n_in,
                              void* d_out, int out_size) {
    const int*   tokens = (const int*)  d_in[0];
    const float* emb    = (const float*)d_in[1];
    const float* wq = (const float*)d_in[2];
    const float* bq = (const float*)d_in[3];
    const float* wk = (const float*)d_in[4];
    const float* bk = (const float*)d_in[5];
    const float* wv = (const float*)d_in[6];
    const float* bv = (const float*)d_in[7];
    const float* wo = (const float*)d_in[8];
    const float* bo = (const float*)d_in[9];
    const float* w1 = (const float*)d_in[10];
    const float* b1 = (const float*)d_in[11];
    const float* w2 = (const float*)d_in[12];
    const float* b2 = (const float*)d_in[13];
    const float* w3 = (const float*)d_in[14];
    const float* b3 = (const float*)d_in[15];
    const float* g1 = (const float*)d_in[16];
    const float* g2 = (const float*)d_in[17];
    const float* gpost = (const float*)d_in[18];
    const float* fcos  = (const float*)d_in[19];
    const float* fsin  = (const float*)d_in[20];
    float* out = (float*)d_out;

    float *x, *q, *k, *v, *f1, *f2;
    __nv_bfloat16 *hH, *hL, *oH, *oL, *f1H, *f1L;
    __nv_bfloat16 *wqH, *wqL, *wkH, *wkL, *wvH, *wvL, *woH, *woL;
    __nv_bfloat16 *w1H, *w1L, *w2H, *w2L, *w3H, *w3L, *ebH, *ebL;
    cudaGetSymbolAddress((void**)&x,  g_x);
    cudaGetSymbolAddress((void**)&q,  g_q);
    cudaGetSymbolAddress((void**)&k,  g_k);
    cudaGetSymbolAddress((void**)&v,  g_v);
    cudaGetSymbolAddress((void**)&f1, g_f1);
    cudaGetSymbolAddress((void**)&f2, g_f2);
    cudaGetSymbolAddress((void**)&hH, g_hH);   cudaGetSymbolAddress((void**)&hL, g_hL);
    cudaGetSymbolAddress((void**)&oH, g_oH);   cudaGetSymbolAddress((void**)&oL, g_oL);
    cudaGetSymbolAddress((void**)&f1H, g_f1H); cudaGetSymbolAddress((void**)&f1L, g_f1L);
    cudaGetSymbolAddress((void**)&wqH, g_wqH); cudaGetSymbolAddress((void**)&wqL, g_wqL);
    cudaGetSymbolAddress((void**)&wkH, g_wkH); cudaGetSymbolAddress((void**)&wkL, g_wkL);
    cudaGetSymbolAddress((void**)&wvH, g_wvH); cudaGetSymbolAddress((void**)&wvL, g_wvL);
    cudaGetSymbolAddress((void**)&woH, g_woH); cudaGetSymbolAddress((void**)&woL, g_woL);
    cudaGetSymbolAddress((void**)&w1H, g_w1H); cudaGetSymbolAddress((void**)&w1L, g_w1L);
    cudaGetSymbolAddress((void**)&w2H, g_w2H); cudaGetSymbolAddress((void**)&w2L, g_w2L);
    cudaGetSymbolAddress((void**)&w3H, g_w3H); cudaGetSymbolAddress((void**)&w3L, g_w3L);
    cudaGetSymbolAddress((void**)&ebH, g_ebH); cudaGetSymbolAddress((void**)&ebL, g_ebL);

    cudaFuncSetAttribute(gemm_bb_kernel,
                         cudaFuncAttributeMaxDynamicSharedMemorySize, G_SMEM);

    // ---- one-time conversions (inside graph; ~0.2 ms total) ----
    esplit_kernel<<<(VV * DD) / (256 * 4), 256>>>(emb, ebH, ebL);
    dim3 tb(32, 8);
    for (int l = 0; l < NL; l++) {
        tsplit_kernel<<<dim3(DD / 32, DD / 32), tb>>>(wq + (size_t)l * DD * DD, wqH + (size_t)l * DD * DD, wqL + (size_t)l * DD * DD, DD, DD);
        tsplit_kernel<<<dim3(KVN / 32, DD / 32), tb>>>(wk + (size_t)l * DD * KVN, wkH + (size_t)l * DD * KVN, wkL + (size_t)l * DD * KVN, DD, KVN);
        tsplit_kernel<<<dim3(KVN / 32, DD / 32), tb>>>(wv + (size_t)l * DD * KVN, wvH + (size_t)l * DD * KVN, wvL + (size_t)l * DD * KVN, DD, KVN);
        tsplit_kernel<<<dim3(DD / 32, DD / 32), tb>>>(wo + (size_t)l * DD * DD, woH + (size_t)l * DD * DD, woL + (size_t)l * DD * DD, DD, DD);
        tsplit_kernel<<<dim3(FD / 32, DD / 32), tb>>>(w1 + (size_t)l * DD * FD, w1H + (size_t)l * DD * FD, w1L + (size_t)l * DD * FD, DD, FD);
        tsplit_kernel<<<dim3(FD / 32, DD / 32), tb>>>(w2 + (size_t)l * DD * FD, w2H + (size_t)l * DD * FD, w2L + (size_t)l * DD * FD, DD, FD);
        tsplit_kernel<<<dim3(DD / 32, FD / 32), tb>>>(w3 + (size_t)l * FD * DD, w3H + (size_t)l * FD * DD, w3L + (size_t)l * FD * DD, FD, DD);
    }

    embed_kernel<<<MM, 256>>>(tokens, emb, x);

    const int GY = MM / 128;    // 32
    for (int l = 0; l < NL; l++) {
        rmsnorm_split_kernel<<<MM, 256>>>(x, g1 + (size_t)l * DD, hH, hL);

        gemm_bb_kernel<<<dim3(DD / 128, GY), 256, G_SMEM>>>(
            hH, hL, wqH + (size_t)l * DD * DD, wqL + (size_t)l * DD * DD,
            bq + (size_t)l * DD, nullptr, q, DD, DD);
        gemm_bb_kernel<<<dim3(KVN / 128, GY), 256, G_SMEM>>>(
            hH, hL, wkH + (size_t)l * DD * KVN, wkL + (size_t)l * DD * KVN,
            bk + (size_t)l * KVN, nullptr, k, KVN, DD);
        gemm_bb_kernel<<<dim3(KVN / 128, GY), 256, G_SMEM>>>(
            hH, hL, wvH + (size_t)l * DD * KVN, wvL + (size_t)l * DD * KVN,
            bv + (size_t)l * KVN, nullptr, v, KVN, DD);

        int tq = MM * HH * 32, tk = MM * KVH * 32;
        rope_kernel<<<(tq + 255) / 256, 256>>>(q, fcos, fsin, HH, tq);
        rope_kernel<<<(tk + 255) / 256, 256>>>(k, fcos, fsin, KVH, tk);

        attn_tc_kernel<<<dim3(SS / 64, HH, BB), 128>>>(q, k, v, oH, oL);

        gemm_bb_kernel<<<dim3(DD / 128, GY), 256, G_SMEM>>>(
            oH, oL, woH + (size_t)l * DD * DD, woL + (size_t)l * DD * DD,
            bo + (size_t)l * DD, x, x, DD, DD);

        rmsnorm_split_kernel<<<MM, 256>>>(x, g2 + (size_t)l * DD, hH, hL);

        int gnx = (FD + 127) / 128;   // 22
        gemm_bb_kernel<<<dim3(gnx, GY), 256, G_SMEM>>>(
            hH, hL, w1H + (size_t)l * DD * FD, w1L + (size_t)l * DD * FD,
            b1 + (size_t)l * FD, nullptr, f1, FD, DD);
        gemm_bb_kernel<<<dim3(gnx, GY), 256, G_SMEM>>>(
            hH, hL, w2H + (size_t)l * DD * FD, w2L + (size_t)l * DD * FD,
            b2 + (size_t)l * FD, nullptr, f2, FD, DD);

        silumul_split_kernel<<<(MM * (FD / 2)) / 256, 256>>>(f1, f2, f1H, f1L);

        gemm_bb_kernel<<<dim3(DD / 128, GY), 256, G_SMEM>>>(
            f1H, f1L, w3H + (size_t)l * FD * DD, w3L + (size_t)l * FD * DD,
            b3 + (size_t)l * DD, x, x, DD, FD);
    }

    rmsnorm_split_kernel<<<MM, 256>>>(x, gpost, hH, hL);
    gemm_bb_kernel<<<dim3(VV / 128, GY), 256, G_SMEM>>>(
        hH, hL, ebH, ebL, nullptr, nullptr, out, VV, DD);
}

// round 11
// speedup vs baseline: 2.0582x; 1.0794x over previous
#include <cuda_runtime.h>
#include <cuda_bf16.h>
#include <math.h>
#include <stdint.h>

// Problem dims (fixed by the dataset)
#define BB   2
#define SS   2048
#define DD   1024
#define HH   16
#define KVH  8
#define DK   64
#define FD   2752
#define NL   4
#define VV   32000
#define MM   (BB*SS)          // 4096 token rows
#define KVN  (KVH*DK)         // 512

// ---------------- scratch (device globals: no allocations allowed) ----------
__device__ float g_x [MM*DD];
__device__ float g_q [MM*DD];
__device__ float g_k [MM*KVN];
__device__ float g_v [MM*KVN];
__device__ float g_f1[(size_t)MM*FD];
__device__ float g_f2[(size_t)MM*FD];

// split activations
__device__ __nv_bfloat16 g_hH [MM*DD],  g_hL [MM*DD];
__device__ __nv_bfloat16 g_oH [MM*DD],  g_oL [MM*DD];
__device__ __nv_bfloat16 g_f1H[(size_t)MM*FD], g_f1L[(size_t)MM*FD];

// split transposed weights ([N][K] layout)
__device__ __nv_bfloat16 g_wqH[(size_t)NL*DD*DD],  g_wqL[(size_t)NL*DD*DD];
__device__ __nv_bfloat16 g_wkH[(size_t)NL*DD*KVN], g_wkL[(size_t)NL*DD*KVN];
__device__ __nv_bfloat16 g_wvH[(size_t)NL*DD*KVN], g_wvL[(size_t)NL*DD*KVN];
__device__ __nv_bfloat16 g_woH[(size_t)NL*DD*DD],  g_woL[(size_t)NL*DD*DD];
__device__ __nv_bfloat16 g_w1H[(size_t)NL*DD*FD],  g_w1L[(size_t)NL*DD*FD];
__device__ __nv_bfloat16 g_w2H[(size_t)NL*DD*FD],  g_w2L[(size_t)NL*DD*FD];
__device__ __nv_bfloat16 g_w3H[(size_t)NL*FD*DD],  g_w3L[(size_t)NL*FD*DD];
__device__ __nv_bfloat16 g_ebH[(size_t)VV*DD],     g_ebL[(size_t)VV*DD];

// ---------------- bf16 split helper ----------------
__device__ __forceinline__ void split2(float x0, float x1,
                                       unsigned &hi, unsigned &lo) {
    __nv_bfloat162 h = __floats2bfloat162_rn(x0, x1);
    float h0 = __bfloat162float(h.x);
    float h1 = __bfloat162float(h.y);
    __nv_bfloat162 l = __floats2bfloat162_rn(x0 - h0, x1 - h1);
    hi = *reinterpret_cast<unsigned*>(&h);
    lo = *reinterpret_cast<unsigned*>(&l);
}

// ---------------- embedding gather ----------------
__global__ void embed_kernel(const int* __restrict__ tokens,
                             const float* __restrict__ emb,
                             float* __restrict__ x) {
    int row = blockIdx.x;
    int tok = tokens[row];
    const float4* src = (const float4*)(emb + (size_t)tok * DD);
    float4*       dst = (float4*)(x + (size_t)row * DD);
    dst[threadIdx.x] = src[threadIdx.x];
}

// ---------------- elementwise split (embed table) ----------------
__global__ void esplit_kernel(const float* __restrict__ W,
                              __nv_bfloat16* __restrict__ H,
                              __nv_bfloat16* __restrict__ L) {
    size_t i = ((size_t)blockIdx.x * 256 + threadIdx.x) * 4;
    float4 v = *(const float4*)(W + i);
    unsigned h0, l0, h1, l1;
    split2(v.x, v.y, h0, l0);
    split2(v.z, v.w, h1, l1);
    *(uint2*)(H + i) = make_uint2(h0, h1);
    *(uint2*)(L + i) = make_uint2(l0, l1);
}

// ---------------- transpose + split: W[K][N] -> H/L[N][K] ----------------
__global__ void tsplit_kernel(const float* __restrict__ W,
                              __nv_bfloat16* __restrict__ H,
                              __nv_bfloat16* __restrict__ L, int K, int N) {
    __shared__ float tile[32][33];
    int n0 = blockIdx.x * 32, k0 = blockIdx.y * 32;
    int tx = threadIdx.x, ty = threadIdx.y;
    #pragma unroll
    for (int i = 0; i < 32; i += 8)
        tile[ty + i][tx] = W[(size_t)(k0 + ty + i) * N + n0 + tx];
    __syncthreads();
    #pragma unroll
    for (int i = 0; i < 32; i += 8) {
        int n = n0 + ty + i, k = k0 + tx;
        float v = tile[tx][ty + i];
        __nv_bfloat16 h = __float2bfloat16_rn(v);
        H[(size_t)n * K + k] = h;
        L[(size_t)n * K + k] = __float2bfloat16_rn(v - __bfloat162float(h));
    }
}

// ---------------- rmsnorm -> split output ----------------
__global__ void rmsnorm_split_kernel(const float* __restrict__ x,
                                     const float* __restrict__ g,
                                     __nv_bfloat16* __restrict__ H,
                                     __nv_bfloat16* __restrict__ L) {
    int row = blockIdx.x;
    const float4* xr = (const float4*)(x + (size_t)row * DD);
    float4 v = xr[threadIdx.x];
    float ss = v.x*v.x + v.y*v.y + v.z*v.z + v.w*v.w;
    #pragma unroll
    for (int o = 16; o; o >>= 1) ss += __shfl_xor_sync(0xffffffffu, ss, o);
    __shared__ float red[8];
    if ((threadIdx.x & 31) == 0) red[threadIdx.x >> 5] = ss;
    __syncthreads();
    if (threadIdx.x < 8) {
        float r = red[threadIdx.x];
        #pragma unroll
        for (int o = 4; o; o >>= 1) r += __shfl_xor_sync(0xffu, r, o);
        if (threadIdx.x == 0) red[0] = r;
    }
    __syncthreads();
    float inv = rsqrtf(red[0] * (1.0f / DD) + 1e-6f);
    const float4* g4 = (const float4*)g;
    float4 gg = g4[threadIdx.x];
    float o0 = v.x*inv*gg.x, o1 = v.y*inv*gg.y, o2 = v.z*inv*gg.z, o3 = v.w*inv*gg.w;
    unsigned h0, l0, h1, l1;
    split2(o0, o1, h0, l0);
    split2(o2, o3, h1, l1);
    size_t base = (size_t)row * DD + threadIdx.x * 4;
    *(uint2*)(H + base) = make_uint2(h0, h1);
    *(uint2*)(L + base) = make_uint2(l0, l1);
}

// ---------------- rope (interleaved pairs) ----------------
__global__ void rope_kernel(float* __restrict__ buf,
                            const float* __restrict__ cosb,
                            const float* __restrict__ sinb,
                            int nheads, int total) {
    int idx = blockIdx.x * blockDim.x + threadIdx.x;
    if (idx >= total) return;
    int p    = idx & 31;
    int hrow = idx >> 5;
    int row  = hrow / nheads;
    int s    = row & (SS - 1);
    float c  = cosb[s * 32 + p];
    float sn = sinb[s * 32 + p];
    float* base = buf + (size_t)hrow * DK + p * 2;
    float xr = base[0], xi = base[1];
    base[0] = xr * c - xi * sn;
    base[1] = xr * sn + xi * c;
}

#define BF16MMA(D, Ar, Br)                                                    \
    asm volatile(                                                             \
        "mma.sync.aligned.m16n8k16.row.col.f32.bf16.bf16.f32 "                \
        "{%0,%1,%2,%3}, {%4,%5,%6,%7}, {%8,%9}, {%0,%1,%2,%3};"               \
        : "+f"(D[0]), "+f"(D[1]), "+f"(D[2]), "+f"(D[3])                      \
        : "r"(Ar[0]), "r"(Ar[1]), "r"(Ar[2]), "r"(Ar[3]),                     \
          "r"(Br[0]), "r"(Br[1]))

#define LDSM4(R0, R1, R2, R3, ADDR)                                           \
    asm volatile("ldmatrix.sync.aligned.m8n8.x4.shared.b16 {%0,%1,%2,%3}, [%4];" \
        : "=r"(R0), "=r"(R1), "=r"(R2), "=r"(R3) : "r"(ADDR))

// ======== flash attention v2, tensor-core, 3xBF16 split, causal, GQA =======
#define KSTR 72
__global__ __launch_bounds__(128)
void attn_tc_kernel(const float* __restrict__ Q, const float* __restrict__ K,
                    const float* __restrict__ V,
                    __nv_bfloat16* __restrict__ OH, __nv_bfloat16* __restrict__ OL) {
    __shared__ unsigned KsH[32][KSTR], KsL[32][KSTR];
    __shared__ unsigned VsH[32][KSTR], VsL[32][KSTR];

    const int qb   = gridDim.x - 1 - blockIdx.x;
    const int hd   = blockIdx.y;
    const int b    = blockIdx.z;
    const int kh   = hd >> 1;
    const int t    = threadIdx.x;
    const int lane = t & 31;
    const int w    = t >> 5;
    const int lq   = lane >> 2;
    const int lr   = lane & 3;

    unsigned qaH[4][4], qaL[4][4];
    {
        const int r0 = qb * 64 + w * 16 + lq;
        const float* q0p = Q + ((size_t)(b * SS + r0) * HH + hd) * DK;
        const float* q1p = q0p + (size_t)8 * HH * DK;
        #pragma unroll
        for (int kb = 0; kb < 4; kb++) {
            float2 v0 = *(const float2*)(q0p + kb * 16 + 2 * lr);
            float2 v1 = *(const float2*)(q1p + kb * 16 + 2 * lr);
            float2 v2 = *(const float2*)(q0p + kb * 16 + 8 + 2 * lr);
            float2 v3 = *(const float2*)(q1p + kb * 16 + 8 + 2 * lr);
            split2(v0.x * 0.125f, v0.y * 0.125f, qaH[kb][0], qaL[kb][0]);
            split2(v1.x * 0.125f, v1.y * 0.125f, qaH[kb][1], qaL[kb][1]);
            split2(v2.x * 0.125f, v2.y * 0.125f, qaH[kb][2], qaL[kb][2]);
            split2(v3.x * 0.125f, v3.y * 0.125f, qaH[kb][3], qaL[kb][3]);
        }
    }

    float acc[8][4] = {};
    float m0 = -1e30f, m1 = -1e30f, l0 = 0.f, l1 = 0.f;

    const int ntiles = qb + 1;
    for (int kt = 0; kt < ntiles; kt++) {
        const int kbase = kt * 64;
        if (kt) __syncthreads();
        {
            int krow = t >> 1, hf = t & 1;
            const float* kp_ = K + ((size_t)(b * SS + kbase + krow) * KVH + kh) * DK + hf * 32;
            #pragma unroll
            for (int i = 0; i < 8; i++) {
                float4 kv = ((const float4*)kp_)[i];
                int dp = hf * 16 + i * 2;
                split2(kv.x, kv.y, KsH[dp][krow],     KsL[dp][krow]);
                split2(kv.z, kv.w, KsH[dp + 1][krow], KsL[dp + 1][krow]);
            }
        }
        {
            int kp2 = t >> 2, q4 = t & 3;
            const float* vr0 = V + ((size_t)(b * SS + kbase + 2 * kp2) * KVH + kh) * DK + q4 * 16;
            const float* vr1 = vr0 + (size_t)KVH * DK;
            #pragma unroll
            for (int i = 0; i < 4; i++) {
                float4 a = ((const float4*)vr0)[i];
                float4 c = ((const float4*)vr1)[i];
                int d = q4 * 16 + i * 4;
                split2(a.x, c.x, VsH[kp2][d],     VsL[kp2][d]);
                split2(a.y, c.y, VsH[kp2][d + 1], VsL[kp2][d + 1]);
                split2(a.z, c.z, VsH[kp2][d + 2], VsL[kp2][d + 2]);
                split2(a.w, c.w, VsH[kp2][d + 3], VsL[kp2][d + 3]);
            }
        }
        __syncthreads();

        float s[8][4] = {};
        #pragma unroll
        for (int kb = 0; kb < 4; kb++) {
            unsigned kfH[8][2], kfL[8][2];
            #pragma unroll
            for (int ni = 0; ni < 8; ni++) {
                kfH[ni][0] = KsH[kb * 8 + lr][ni * 8 + lq];
                kfH[ni][1] = KsH[kb * 8 + lr + 4][ni * 8 + lq];
                kfL[ni][0] = KsL[kb * 8 + lr][ni * 8 + lq];
                kfL[ni][1] = KsL[kb * 8 + lr + 4][ni * 8 + lq];
            }
            #pragma unroll
            for (int ni = 0; ni < 8; ni++) {
                BF16MMA(s[ni], qaH[kb], kfH[ni]);
                BF16MMA(s[ni], qaL[kb], kfH[ni]);
                BF16MMA(s[ni], qaH[kb], kfL[ni]);
            }
        }

        if (kt == qb) {
            int row0 = qb * 64 + w * 16 + lq;
            #pragma unroll
            for (int ni = 0; ni < 8; ni++) {
                int col = kbase + ni * 8 + 2 * lr;
                if (col     > row0)     s[ni][0] = -1e30f;
                if (col + 1 > row0)     s[ni][1] = -1e30f;
                if (col     > row0 + 8) s[ni][2] = -1e30f;
                if (col + 1 > row0 + 8) s[ni][3] = -1e30f;
            }
        }

        float mt0 = -1e30f, mt1 = -1e30f;
        #pragma unroll
        for (int ni = 0; ni < 8; ni++) {
            mt0 = fmaxf(mt0, fmaxf(s[ni][0], s[ni][1]));
            mt1 = fmaxf(mt1, fmaxf(s[ni][2], s[ni][3]));
        }
        mt0 = fmaxf(mt0, __shfl_xor_sync(0xffffffffu, mt0, 1));
        mt0 = fmaxf(mt0, __shfl_xor_sync(0xffffffffu, mt0, 2));
        mt1 = fmaxf(mt1, __shfl_xor_sync(0xffffffffu, mt1, 1));
        mt1 = fmaxf(mt1, __shfl_xor_sync(0xffffffffu, mt1, 2));
        float mn0 = fmaxf(m0, mt0), mn1 = fmaxf(m1, mt1);
        float c0 = __expf(m0 - mn0), c1 = __expf(m1 - mn1);
        m0 = mn0; m1 = mn1;
        float rs0 = 0.f, rs1 = 0.f;
        #pragma unroll
        for (int ni = 0; ni < 8; ni++) {
            s[ni][0] = __expf(s[ni][0] - mn0);
            s[ni][1] = __expf(s[ni][1] - mn0);
            s[ni][2] = __expf(s[ni][2] - mn1);
            s[ni][3] = __expf(s[ni][3] - mn1);
            rs0 += s[ni][0] + s[ni][1];
            rs1 += s[ni][2] + s[ni][3];
        }
        rs0 += __shfl_xor_sync(0xffffffffu, rs0, 1);
        rs0 += __shfl_xor_sync(0xffffffffu, rs0, 2);
        rs1 += __shfl_xor_sync(0xffffffffu, rs1, 1);
        rs1 += __shfl_xor_sync(0xffffffffu, rs1, 2);
        l0 = l0 * c0 + rs0;
        l1 = l1 * c1 + rs1;
        #pragma unroll
        for (int dn = 0; dn < 8; dn++) {
            acc[dn][0] *= c0; acc[dn][1] *= c0;
            acc[dn][2] *= c1; acc[dn][3] *= c1;
        }

        #pragma unroll
        for (int kb = 0; kb < 4; kb++) {
            unsigned aPH[4], aPL[4];
            split2(s[2*kb][0],   s[2*kb][1],   aPH[0], aPL[0]);
            split2(s[2*kb][2],   s[2*kb][3],   aPH[1], aPL[1]);
            split2(s[2*kb+1][0], s[2*kb+1][1], aPH[2], aPL[2]);
            split2(s[2*kb+1][2], s[2*kb+1][3], aPH[3], aPL[3]);
            #pragma unroll
            for (int dn = 0; dn < 8; dn++) {
                unsigned vfH[2], vfL[2];
                vfH[0] = VsH[kb * 8 + lr][dn * 8 + lq];
                vfH[1] = VsH[kb * 8 + lr + 4][dn * 8 + lq];
                vfL[0] = VsL[kb * 8 + lr][dn * 8 + lq];
                vfL[1] = VsL[kb * 8 + lr + 4][dn * 8 + lq];
                BF16MMA(acc[dn], aPH, vfH);
                BF16MMA(acc[dn], aPL, vfH);
                BF16MMA(acc[dn], aPH, vfL);
            }
        }
    }

    float inv0 = 1.f / l0, inv1 = 1.f / l1;
    int row0 = qb * 64 + w * 16 + lq;
    size_t b0 = ((size_t)(b * SS + row0) * HH + hd) * DK;
    size_t b1 = b0 + (size_t)8 * HH * DK;
    #pragma unroll
    for (int dn = 0; dn < 8; dn++) {
        int d = dn * 8 + 2 * lr;
        unsigned h_, l_;
        split2(acc[dn][0] * inv0, acc[dn][1] * inv0, h_, l_);
        *(unsigned*)(OH + b0 + d) = h_;
        *(unsigned*)(OL + b0 + d) = l_;
        split2(acc[dn][2] * inv1, acc[dn][3] * inv1, h_, l_);
        *(unsigned*)(OH + b1 + d) = h_;
        *(unsigned*)(OL + b1 + d) = l_;
    }
}

// ========== pure-bf16 split GEMM, cp.async 3-stage, ldmatrix ===============
// C[M,N] = (AH+AL)[M][K] @ (BH+BL)[N][K]^T (+bias)(+residual), fp32 out.
// Block tile 128xBN (BN=128 or 256), 256 threads, 8 warps (2x4),
// warp tile 64x(BN/4).
#define G_BK 32
#define G_RS 80                     // smem row stride bytes (64 data + 16 pad)

__device__ __forceinline__ unsigned smem_u32(const void* p) {
    unsigned r;
    asm("{ .reg .u64 t; cvta.to.shared.u64 t, %1; cvt.u32.u64 %0, t; }" : "=r"(r) : "l"(p));
    return r;
}

template<int BN>
__global__ __launch_bounds__(256)
void gemm_bb_kernel(const __nv_bfloat16* __restrict__ AH_, const __nv_bfloat16* __restrict__ AL_,
                    const __nv_bfloat16* __restrict__ BH_, const __nv_bfloat16* __restrict__ BL_,
                    const float* __restrict__ bias, const float* __restrict__ res,
                    float* __restrict__ C, int Nd, int Kd) {
    constexpr int NG      = BN / 64;                 // b-frag groups per warp
    constexpr unsigned OFF_AL = 128 * G_RS;
    constexpr unsigned OFF_BH = 256 * G_RS;
    constexpr unsigned OFF_BL = (256 + BN) * G_RS;
    constexpr unsigned STAGE  = (256 + 2 * BN) * G_RS;
    constexpr int CH_B    = BN * 4;                  // cp.async chunks per B tile

    extern __shared__ char smem[];
    const unsigned sbase = smem_u32(smem);
    const int t    = threadIdx.x;
    const int lane = t & 31;
    const int warp = t >> 5;
    const int wm   = warp >> 2;
    const int wn   = warp & 3;
    const int bm   = blockIdx.y * 128;
    const int bn   = blockIdx.x * BN;

    float acc[4][2 * NG][4] = {};
    const int nkt = Kd / G_BK;

    auto issue_stage = [&](int kt) {
        const int k0 = kt * G_BK;
        unsigned sb = sbase + (kt % 3) * STAGE;
        // A tiles: 1024 chunks (AH 512, AL 512)
        #pragma unroll
        for (int i = 0; i < 4; i++) {
            int c = t + i * 256;
            const __nv_bfloat16* base = (c < 512) ? AH_ : AL_;
            unsigned offt = (c < 512) ? 0u : OFF_AL;
            int cc = c & 511;
            int row = cc >> 2, quad = cc & 3;
            const __nv_bfloat16* src = base + (size_t)(bm + row) * Kd + k0 + quad * 8;
            unsigned dst = sb + offt + row * G_RS + quad * 16;
            asm volatile("cp.async.cg.shared.global [%0], [%1], 16;"
                         :: "r"(dst), "l"(src) : "memory");
        }
        // B tiles: 2*CH_B chunks total -> BN/32 iterations of 256 threads
        #pragma unroll
        for (int i = 0; i < BN / 32; i++) {
            int c = t + i * 256;
            const __nv_bfloat16* base = (c < CH_B) ? BH_ : BL_;
            unsigned offt = (c < CH_B) ? OFF_BH : OFF_BL;
            int cc = c & (CH_B - 1);
            int row = cc >> 2, quad = cc & 3;
            const __nv_bfloat16* src = base + (size_t)(bn + row) * Kd + k0 + quad * 8;
            unsigned dst = sb + offt + row * G_RS + quad * 16;
            int vsz = (bn + row < Nd) ? 16 : 0;
            asm volatile("cp.async.cg.shared.global [%0], [%1], 16, %2;"
                         :: "r"(dst), "l"(src), "r"(vsz) : "memory");
        }
        asm volatile("cp.async.commit_group;" ::: "memory");
    };

    issue_stage(0);
    issue_stage(1);

    const int m0 = wm * 64;
    const int n0 = wn * (BN / 4);
    const int lq = lane >> 2;
    const int lr = lane & 3;
    const unsigned aRowOff = (unsigned)(lane & 15) * G_RS + (unsigned)(lane >> 4) * 16;
    const unsigned bRowOff = ((unsigned)((lane >> 4) * 8 + (lane & 7))) * G_RS
                           + (unsigned)((lane >> 3) & 1) * 16;

    for (int kt = 0; kt < nkt; kt++) {
        asm volatile("cp.async.wait_group 1;" ::: "memory");
        __syncthreads();
        if (kt + 2 < nkt) issue_stage(kt + 2);
        else asm volatile("cp.async.commit_group;" ::: "memory");

        const unsigned stb = sbase + (kt % 3) * STAGE;
        #pragma unroll
        for (int ks = 0; ks < 2; ks++) {
            unsigned aH[4][4], aL[4][4], bH[NG][4], bL[NG][4];
            const unsigned ksb = ks * 32;
            #pragma unroll
            for (int mi = 0; mi < 4; mi++) {
                unsigned ah = stb + (m0 + mi * 16) * G_RS + ksb + aRowOff;
                unsigned al = ah + OFF_AL;
                LDSM4(aH[mi][0], aH[mi][1], aH[mi][2], aH[mi][3], ah);
                LDSM4(aL[mi][0], aL[mi][1], aL[mi][2], aL[mi][3], al);
            }
            #pragma unroll
            for (int ng = 0; ng < NG; ng++) {
                unsigned bhh = stb + OFF_BH + (n0 + ng * 16) * G_RS + ksb + bRowOff;
                unsigned bll = bhh + (unsigned)(BN * G_RS);
                LDSM4(bH[ng][0], bH[ng][1], bH[ng][2], bH[ng][3], bhh);
                LDSM4(bL[ng][0], bL[ng][1], bL[ng][2], bL[ng][3], bll);
            }
            #pragma unroll
            for (int mi = 0; mi < 4; mi++)
                #pragma unroll
                for (int ng = 0; ng < NG; ng++) {
                    float* acc0 = acc[mi][ng * 2];
                    float* acc1 = acc[mi][ng * 2 + 1];
                    BF16MMA(acc0, aH[mi], (bH[ng] + 0));
                    BF16MMA(acc0, aL[mi], (bH[ng] + 0));
                    BF16MMA(acc0, aH[mi], (bL[ng] + 0));
                    BF16MMA(acc1, aH[mi], (bH[ng] + 2));
                    BF16MMA(acc1, aL[mi], (bH[ng] + 2));
                    BF16MMA(acc1, aH[mi], (bL[ng] + 2));
                }
        }
    }

    // ---- epilogue
    #pragma unroll
    for (int mi = 0; mi < 4; mi++) {
        int row = bm + m0 + mi * 16 + lq;
        #pragma unroll
        for (int ni = 0; ni < 2 * NG; ni++) {
            int col = bn + n0 + ni * 8 + lr * 2;
            if (col < Nd) {
                float v0 = acc[mi][ni][0], v1 = acc[mi][ni][1];
                float v2 = acc[mi][ni][2], v3 = acc[mi][ni][3];
                if (bias) {
                    float bx = bias[col], by = bias[col + 1];
                    v0 += bx; v1 += by; v2 += bx; v3 += by;
                }
                size_t o0 = (size_t)row * Nd + col;
                size_t o1 = (size_t)(row + 8) * Nd + col;
                if (res) {
                    v0 += res[o0]; v1 += res[o0 + 1];
                    v2 += res[o1]; v3 += res[o1 + 1];
                }
                C[o0] = v0; C[o0 + 1] = v1;
                C[o1] = v2; C[o1 + 1] = v3;
            }
        }
    }
}

#define SM128 ((256 + 2 * 128) * G_RS * 3)    // 122880
#define SM256 ((256 + 2 * 256) * G_RS * 3)    // 184320

// ---------------- silu(f1)*f2 -> split ----------------
__global__ void silumul_split_kernel(const float* __restrict__ f1,
                                     const float* __restrict__ f2,
                                     __nv_bfloat16* __restrict__ H,
                                     __nv_bfloat16* __restrict__ L) {
    size_t i = (size_t)blockIdx.x * 256 + threadIdx.x;   // pair index
    float2 a = ((const float2*)f1)[i];
    float2 b = ((const float2*)f2)[i];
    float g0 = a.x / (1.0f + __expf(-a.x)) * b.x;
    float g1 = a.y / (1.0f + __expf(-a.y)) * b.y;
    unsigned h_, l_;
    split2(g0, g1, h_, l_);
    ((unsigned*)H)[i] = h_;
    ((unsigned*)L)[i] = l_;
}

// ---------------- host driver ----------------
extern "C" void kernel_launch(void* const* d_in, const int* in_sizes, int n_in,
                              void* d_out, int out_size) {
    const int*   tokens = (const int*)  d_in[0];
    const float* emb    = (const float*)d_in[1];
    const float* wq = (const float*)d_in[2];
    const float* bq = (const float*)d_in[3];
    const float* wk = (const float*)d_in[4];
    const float* bk = (const float*)d_in[5];
    const float* wv = (const float*)d_in[6];
    const float* bv = (const float*)d_in[7];
    const float* wo = (const float*)d_in[8];
    const float* bo = (const float*)d_in[9];
    const float* w1 = (const float*)d_in[10];
    const float* b1 = (const float*)d_in[11];
    const float* w2 = (const float*)d_in[12];
    const float* b2 = (const float*)d_in[13];
    const float* w3 = (const float*)d_in[14];
    const float* b3 = (const float*)d_in[15];
    const float* g1 = (const float*)d_in[16];
    const float* g2 = (const float*)d_in[17];
    const float* gpost = (const float*)d_in[18];
    const float* fcos  = (const float*)d_in[19];
    const float* fsin  = (const float*)d_in[20];
    float* out = (float*)d_out;

    float *x, *q, *k, *v, *f1, *f2;
    __nv_bfloat16 *hH, *hL, *oH, *oL, *f1H, *f1L;
    __nv_bfloat16 *wqH, *wqL, *wkH, *wkL, *wvH, *wvL, *woH, *woL;
    __nv_bfloat16 *w1H, *w1L, *w2H, *w2L, *w3H, *w3L, *ebH, *ebL;
    cudaGetSymbolAddress((void**)&x,  g_x);
    cudaGetSymbolAddress((void**)&q,  g_q);
    cudaGetSymbolAddress((void**)&k,  g_k);
    cudaGetSymbolAddress((void**)&v,  g_v);
    cudaGetSymbolAddress((void**)&f1, g_f1);
    cudaGetSymbolAddress((void**)&f2, g_f2);
    cudaGetSymbolAddress((void**)&hH, g_hH);   cudaGetSymbolAddress((void**)&hL, g_hL);
    cudaGetSymbolAddress((void**)&oH, g_oH);   cudaGetSymbolAddress((void**)&oL, g_oL);
    cudaGetSymbolAddress((void**)&f1H, g_f1H); cudaGetSymbolAddress((void**)&f1L, g_f1L);
    cudaGetSymbolAddress((void**)&wqH, g_wqH); cudaGetSymbolAddress((void**)&wqL, g_wqL);
    cudaGetSymbolAddress((void**)&wkH, g_wkH); cudaGetSymbolAddress((void**)&wkL, g_wkL);
    cudaGetSymbolAddress((void**)&wvH, g_wvH); cudaGetSymbolAddress((void**)&wvL, g_wvL);
    cudaGetSymbolAddress((void**)&woH, g_woH); cudaGetSymbolAddress((void**)&woL, g_woL);
    cudaGetSymbolAddress((void**)&w1H, g_w1H); cudaGetSymbolAddress((void**)&w1L, g_w1L);
    cudaGetSymbolAddress((void**)&w2H, g_w2H); cudaGetSymbolAddress((void**)&w2L, g_w2L);
    cudaGetSymbolAddress((void**)&w3H, g_w3H); cudaGetSymbolAddress((void**)&w3L, g_w3L);
    cudaGetSymbolAddress((void**)&ebH, g_ebH); cudaGetSymbolAddress((void**)&ebL, g_ebL);

    cudaFuncSetAttribute(gemm_bb_kernel<128>,
                         cudaFuncAttributeMaxDynamicSharedMemorySize, SM128);
    cudaFuncSetAttribute(gemm_bb_kernel<256>,
                         cudaFuncAttributeMaxDynamicSharedMemorySize, SM256);

    // ---- conversions (inside graph) ----
    esplit_kernel<<<(VV * DD) / (256 * 4), 256>>>(emb, ebH, ebL);
    dim3 tb(32, 8);
    for (int l = 0; l < NL; l++) {
        tsplit_kernel<<<dim3(DD / 32, DD / 32), tb>>>(wq + (size_t)l * DD * DD, wqH + (size_t)l * DD * DD, wqL + (size_t)l * DD * DD, DD, DD);
        tsplit_kernel<<<dim3(KVN / 32, DD / 32), tb>>>(wk + (size_t)l * DD * KVN, wkH + (size_t)l * DD * KVN, wkL + (size_t)l * DD * KVN, DD, KVN);
        tsplit_kernel<<<dim3(KVN / 32, DD / 32), tb>>>(wv + (size_t)l * DD * KVN, wvH + (size_t)l * DD * KVN, wvL + (size_t)l * DD * KVN, DD, KVN);
        tsplit_kernel<<<dim3(DD / 32, DD / 32), tb>>>(wo + (size_t)l * DD * DD, woH + (size_t)l * DD * DD, woL + (size_t)l * DD * DD, DD, DD);
        tsplit_kernel<<<dim3(FD / 32, DD / 32), tb>>>(w1 + (size_t)l * DD * FD, w1H + (size_t)l * DD * FD, w1L + (size_t)l * DD * FD, DD, FD);
        tsplit_kernel<<<dim3(FD / 32, DD / 32), tb>>>(w2 + (size_t)l * DD * FD, w2H + (size_t)l * DD * FD, w2L + (size_t)l * DD * FD, DD, FD);
        tsplit_kernel<<<dim3(DD / 32, FD / 32), tb>>>(w3 + (size_t)l * FD * DD, w3H + (size_t)l * FD * DD, w3L + (size_t)l * FD * DD, FD, DD);
    }

    embed_kernel<<<MM, 256>>>(tokens, emb, x);

    const int GY = MM / 128;    // 32
    for (int l = 0; l < NL; l++) {
        rmsnorm_split_kernel<<<MM, 256>>>(x, g1 + (size_t)l * DD, hH, hL);

        gemm_bb_kernel<256><<<dim3(DD / 256, GY), 256, SM256>>>(
            hH, hL, wqH + (size_t)l * DD * DD, wqL + (size_t)l * DD * DD,
            bq + (size_t)l * DD, nullptr, q, DD, DD);
        gemm_bb_kernel<128><<<dim3(KVN / 128, GY), 256, SM128>>>(
            hH, hL, wkH + (size_t)l * DD * KVN, wkL + (size_t)l * DD * KVN,
            bk + (size_t)l * KVN, nullptr, k, KVN, DD);
        gemm_bb_kernel<128><<<dim3(KVN / 128, GY), 256, SM128>>>(
            hH, hL, wvH + (size_t)l * DD * KVN, wvL + (size_t)l * DD * KVN,
            bv + (size_t)l * KVN, nullptr, v, KVN, DD);

        int tq = MM * HH * 32, tk = MM * KVH * 32;
        rope_kernel<<<(tq + 255) / 256, 256>>>(q, fcos, fsin, HH, tq);
        rope_kernel<<<(tk + 255) / 256, 256>>>(k, fcos, fsin, KVH, tk);

        attn_tc_kernel<<<dim3(SS / 64, HH, BB), 128>>>(q, k, v, oH, oL);

        gemm_bb_kernel<256><<<dim3(DD / 256, GY), 256, SM256>>>(
            oH, oL, woH + (size_t)l * DD * DD, woL + (size_t)l * DD * DD,
            bo + (size_t)l * DD, x, x, DD, DD);

        rmsnorm_split_kernel<<<MM, 256>>>(x, g2 + (size_t)l * DD, hH, hL);

        int gnx = (FD + 255) / 256;   // 11
        gemm_bb_kernel<256><<<dim3(gnx, GY), 256, SM256>>>(
            hH, hL, w1H + (size_t)l * DD * FD, w1L + (size_t)l * DD * FD,
            b1 + (size_t)l * FD, nullptr, f1, FD, DD);
        gemm_bb_kernel<256><<<dim3(gnx, GY), 256, SM256>>>(
            hH, hL, w2H + (size_t)l * DD * FD, w2L + (size_t)l * DD * FD,
            b2 + (size_t)l * FD, nullptr, f2, FD, DD);

        silumul_split_kernel<<<(MM * (FD / 2)) / 256, 256>>>(f1, f2, f1H, f1L);

        gemm_bb_kernel<256><<<dim3(DD / 256, GY), 256, SM256>>>(
            f1H, f1L, w3H + (size_t)l * FD * DD, w3L + (size_t)l * FD * DD,
            b3 + (size_t)l * DD, x, x, DD, FD);
    }

    rmsnorm_split_kernel<<<MM, 256>>>(x, gpost, hH, hL);
    gemm_bb_kernel<256><<<dim3(VV / 256, GY), 256, SM256>>>(
        hH, hL, ebH, ebL, nullptr, nullptr, out, VV, DD);
}

// round 12
// speedup vs baseline: 2.2889x; 1.1121x over previous
#include <cuda_runtime.h>
#include <cuda_bf16.h>
#include <math.h>
#include <stdint.h>

// Problem dims (fixed by the dataset)
#define BB   2
#define SS   2048
#define DD   1024
#define HH   16
#define KVH  8
#define DK   64
#define FD   2752
#define NL   4
#define VV   32000
#define MM   (BB*SS)          // 4096 token rows
#define KVN  (KVH*DK)         // 512

// ---------------- scratch (device globals: no allocations allowed) ----------
__device__ float g_x [MM*DD];
__device__ float g_q [MM*DD];
__device__ float g_kv[MM*1024];
__device__ float g_f1[(size_t)MM*FD];
__device__ float g_f2[(size_t)MM*FD];
__device__ float g_bkv[NL*1024];

// split activations
__device__ __nv_bfloat16 g_hH [MM*DD],  g_hL [MM*DD];
__device__ __nv_bfloat16 g_oH [MM*DD],  g_oL [MM*DD];
__device__ __nv_bfloat16 g_kvH[MM*1024], g_kvL[MM*1024];
__device__ __nv_bfloat16 g_f1H[(size_t)MM*FD], g_f1L[(size_t)MM*FD];

// split transposed weights ([N][K] layout)
__device__ __nv_bfloat16 g_wqH [(size_t)NL*DD*DD],   g_wqL [(size_t)NL*DD*DD];
__device__ __nv_bfloat16 g_wkvH[(size_t)NL*1024*DD], g_wkvL[(size_t)NL*1024*DD];
__device__ __nv_bfloat16 g_woH [(size_t)NL*DD*DD],   g_woL [(size_t)NL*DD*DD];
__device__ __nv_bfloat16 g_w1H [(size_t)NL*DD*FD],   g_w1L [(size_t)NL*DD*FD];
__device__ __nv_bfloat16 g_w2H [(size_t)NL*DD*FD],   g_w2L [(size_t)NL*DD*FD];
__device__ __nv_bfloat16 g_w3H [(size_t)NL*FD*DD],   g_w3L [(size_t)NL*FD*DD];
__device__ __nv_bfloat16 g_ebH [(size_t)VV*DD],      g_ebL [(size_t)VV*DD];

// ---------------- bf16 split helper ----------------
__device__ __forceinline__ void split2(float x0, float x1,
                                       unsigned &hi, unsigned &lo) {
    __nv_bfloat162 h = __floats2bfloat162_rn(x0, x1);
    float h0 = __bfloat162float(h.x);
    float h1 = __bfloat162float(h.y);
    __nv_bfloat162 l = __floats2bfloat162_rn(x0 - h0, x1 - h1);
    hi = *reinterpret_cast<unsigned*>(&h);
    lo = *reinterpret_cast<unsigned*>(&l);
}

__device__ __forceinline__ unsigned smem_u32(const void* p) {
    unsigned r;
    asm("{ .reg .u64 t; cvta.to.shared.u64 t, %1; cvt.u32.u64 %0, t; }" : "=r"(r) : "l"(p));
    return r;
}

// ---------------- embedding gather ----------------
__global__ void embed_kernel(const int* __restrict__ tokens,
                             const float* __restrict__ emb,
                             float* __restrict__ x) {
    int row = blockIdx.x;
    int tok = tokens[row];
    const float4* src = (const float4*)(emb + (size_t)tok * DD);
    float4*       dst = (float4*)(x + (size_t)row * DD);
    dst[threadIdx.x] = src[threadIdx.x];
}

// ---------------- elementwise split (embed table) ----------------
__global__ void esplit_kernel(const float* __restrict__ W,
                              __nv_bfloat16* __restrict__ H,
                              __nv_bfloat16* __restrict__ L) {
    size_t i = ((size_t)blockIdx.x * 256 + threadIdx.x) * 4;
    float4 v = *(const float4*)(W + i);
    unsigned h0, l0, h1, l1;
    split2(v.x, v.y, h0, l0);
    split2(v.z, v.w, h1, l1);
    *(uint2*)(H + i) = make_uint2(h0, h1);
    *(uint2*)(L + i) = make_uint2(l0, l1);
}

// ---------------- transpose + split: W[K][N] -> H/L[N][K] ----------------
__global__ void tsplit_kernel(const float* __restrict__ W,
                              __nv_bfloat16* __restrict__ H,
                              __nv_bfloat16* __restrict__ L, int K, int N) {
    __shared__ float tile[32][33];
    int n0 = blockIdx.x * 32, k0 = blockIdx.y * 32;
    int tx = threadIdx.x, ty = threadIdx.y;
    #pragma unroll
    for (int i = 0; i < 32; i += 8)
        tile[ty + i][tx] = W[(size_t)(k0 + ty + i) * N + n0 + tx];
    __syncthreads();
    #pragma unroll
    for (int i = 0; i < 32; i += 8) {
        int n = n0 + ty + i, k = k0 + tx;
        float v = tile[tx][ty + i];
        __nv_bfloat16 h = __float2bfloat16_rn(v);
        H[(size_t)n * K + k] = h;
        L[(size_t)n * K + k] = __float2bfloat16_rn(v - __bfloat162float(h));
    }
}

// ---------------- bias concat for merged KV GEMM ----------------
__global__ void bkv_kernel(const float* __restrict__ bk, const float* __restrict__ bv,
                           float* __restrict__ bkv) {
    int l = blockIdx.x, t = threadIdx.x;   // 512 threads
    bkv[l * 1024 + t]       = bk[l * 512 + t];
    bkv[l * 1024 + 512 + t] = bv[l * 512 + t];
}

// ---------------- rmsnorm -> split output ----------------
__global__ void rmsnorm_split_kernel(const float* __restrict__ x,
                                     const float* __restrict__ g,
                                     __nv_bfloat16* __restrict__ H,
                                     __nv_bfloat16* __restrict__ L) {
    int row = blockIdx.x;
    const float4* xr = (const float4*)(x + (size_t)row * DD);
    float4 v = xr[threadIdx.x];
    float ss = v.x*v.x + v.y*v.y + v.z*v.z + v.w*v.w;
    #pragma unroll
    for (int o = 16; o; o >>= 1) ss += __shfl_xor_sync(0xffffffffu, ss, o);
    __shared__ float red[8];
    if ((threadIdx.x & 31) == 0) red[threadIdx.x >> 5] = ss;
    __syncthreads();
    if (threadIdx.x < 8) {
        float r = red[threadIdx.x];
        #pragma unroll
        for (int o = 4; o; o >>= 1) r += __shfl_xor_sync(0xffu, r, o);
        if (threadIdx.x == 0) red[0] = r;
    }
    __syncthreads();
    float inv = rsqrtf(red[0] * (1.0f / DD) + 1e-6f);
    const float4* g4 = (const float4*)g;
    float4 gg = g4[threadIdx.x];
    float o0 = v.x*inv*gg.x, o1 = v.y*inv*gg.y, o2 = v.z*inv*gg.z, o3 = v.w*inv*gg.w;
    unsigned h0, l0, h1, l1;
    split2(o0, o1, h0, l0);
    split2(o2, o3, h1, l1);
    size_t base = (size_t)row * DD + threadIdx.x * 4;
    *(uint2*)(H + base) = make_uint2(h0, h1);
    *(uint2*)(L + base) = make_uint2(l0, l1);
}

// ---------------- rope for q (interleaved pairs) ----------------
__global__ void rope_kernel(float* __restrict__ buf,
                            const float* __restrict__ cosb,
                            const float* __restrict__ sinb,
                            int nheads, int total) {
    int idx = blockIdx.x * blockDim.x + threadIdx.x;
    if (idx >= total) return;
    int p    = idx & 31;
    int hrow = idx >> 5;
    int row  = hrow / nheads;
    int s    = row & (SS - 1);
    float c  = cosb[s * 32 + p];
    float sn = sinb[s * 32 + p];
    float* base = buf + (size_t)hrow * DK + p * 2;
    float xr = base[0], xi = base[1];
    base[0] = xr * c - xi * sn;
    base[1] = xr * sn + xi * c;
}

// ---------------- kv: rope(k part) + split into bf16 hi/lo ----------------
__global__ void kvsplit_rope_kernel(const float* __restrict__ kv,
                                    const float* __restrict__ cosb,
                                    const float* __restrict__ sinb,
                                    __nv_bfloat16* __restrict__ H,
                                    __nv_bfloat16* __restrict__ L) {
    int row = blockIdx.x;
    int s   = row & (SS - 1);
    for (int pp = threadIdx.x; pp < 512; pp += 256) {
        int col = pp * 2;
        float2 v = *(const float2*)(kv + (size_t)row * 1024 + col);
        if (col < 512) {
            int p = (col & 63) >> 1;
            float c = cosb[s * 32 + p], sn = sinb[s * 32 + p];
            float xr = v.x, xi = v.y;
            v.x = xr * c - xi * sn;
            v.y = xr * sn + xi * c;
        }
        unsigned h_, l_;
        split2(v.x, v.y, h_, l_);
        ((unsigned*)H)[(size_t)row * 512 + pp] = h_;
        ((unsigned*)L)[(size_t)row * 512 + pp] = l_;
    }
}

#define BF16MMA(D, Ar, Br)                                                    \
    asm volatile(                                                             \
        "mma.sync.aligned.m16n8k16.row.col.f32.bf16.bf16.f32 "                \
        "{%0,%1,%2,%3}, {%4,%5,%6,%7}, {%8,%9}, {%0,%1,%2,%3};"               \
        : "+f"(D[0]), "+f"(D[1]), "+f"(D[2]), "+f"(D[3])                      \
        : "r"(Ar[0]), "r"(Ar[1]), "r"(Ar[2]), "r"(Ar[3]),                     \
          "r"(Br[0]), "r"(Br[1]))

#define LDSM4(R0, R1, R2, R3, ADDR)                                           \
    asm volatile("ldmatrix.sync.aligned.m8n8.x4.shared.b16 {%0,%1,%2,%3}, [%4];" \
        : "=r"(R0), "=r"(R1), "=r"(R2), "=r"(R3) : "r"(ADDR))

#define LDSM4T(R0, R1, R2, R3, ADDR)                                          \
    asm volatile("ldmatrix.sync.aligned.m8n8.x4.trans.shared.b16 {%0,%1,%2,%3}, [%4];" \
        : "=r"(R0), "=r"(R1), "=r"(R2), "=r"(R3) : "r"(ADDR))

// ======== flash attention v2: cp.async bf16 tiles + ldmatrix, 3x split =====
// K and V tiles stored [key][d] (64 x 128B rows, stride 144B).
// S = Q·K^T: K rows as B-operand [n][k] via non-trans ldmatrix.
// O += P·V: V rows as [k][n] via trans ldmatrix.
#define ARS 144
#define ATILE (64 * ARS)          // 9216
#define ASTAGE (4 * ATILE)        // KsH, KsL, VsH, VsL
#define ASMEM (2 * ASTAGE)        // 73728

__global__ __launch_bounds__(128)
void attn_tc_kernel(const float* __restrict__ Q,
                    const __nv_bfloat16* __restrict__ kvH,
                    const __nv_bfloat16* __restrict__ kvL,
                    __nv_bfloat16* __restrict__ OH, __nv_bfloat16* __restrict__ OL) {
    extern __shared__ char asmem[];
    const unsigned sb0 = smem_u32(asmem);
    const int qb   = gridDim.x - 1 - blockIdx.x;   // heavy blocks first
    const int hd   = blockIdx.y;
    const int b    = blockIdx.z;
    const int kh   = hd >> 1;
    const int t    = threadIdx.x;
    const int lane = t & 31;
    const int w    = t >> 5;
    const int lq   = lane >> 2;
    const int lr   = lane & 3;

    // ---- resident Q fragments (fp32 load + split, once) ----
    unsigned qaH[4][4], qaL[4][4];
    {
        const int r0 = qb * 64 + w * 16 + lq;
        const float* q0p = Q + ((size_t)(b * SS + r0) * HH + hd) * DK;
        const float* q1p = q0p + (size_t)8 * HH * DK;
        #pragma unroll
        for (int kb = 0; kb < 4; kb++) {
            float2 v0 = *(const float2*)(q0p + kb * 16 + 2 * lr);
            float2 v1 = *(const float2*)(q1p + kb * 16 + 2 * lr);
            float2 v2 = *(const float2*)(q0p + kb * 16 + 8 + 2 * lr);
            float2 v3 = *(const float2*)(q1p + kb * 16 + 8 + 2 * lr);
            split2(v0.x * 0.125f, v0.y * 0.125f, qaH[kb][0], qaL[kb][0]);
            split2(v1.x * 0.125f, v1.y * 0.125f, qaH[kb][1], qaL[kb][1]);
            split2(v2.x * 0.125f, v2.y * 0.125f, qaH[kb][2], qaL[kb][2]);
            split2(v3.x * 0.125f, v3.y * 0.125f, qaH[kb][3], qaL[kb][3]);
        }
    }

    float acc[8][4] = {};
    float m0 = -1e30f, m1 = -1e30f, l0 = 0.f, l1 = 0.f;
    const int ntiles = qb + 1;

    const unsigned aOff = (unsigned)(lane & 15) * ARS + (unsigned)(lane >> 4) * 16;
    const unsigned bOff = (unsigned)((lane >> 4) * 8 + (lane & 7)) * ARS
                        + (unsigned)((lane >> 3) & 1) * 16;

    auto issue_tile = [&](int kt) {
        const int kbase = kt * 64;
        unsigned sb = sb0 + (kt & 1) * ASTAGE;
        #pragma unroll
        for (int i = 0; i < 16; i++) {
            int c   = t + i * 128;
            int buf = c >> 9;                  // 0 KsH, 1 KsL, 2 VsH, 3 VsL
            int cc  = c & 511;
            int row = cc >> 3, q8 = cc & 7;
            const __nv_bfloat16* bp = (buf & 1) ? kvL : kvH;
            int voff = (buf >> 1) * 512;
            const __nv_bfloat16* src = bp + (size_t)(b * SS + kbase + row) * 1024
                                          + voff + kh * 64 + q8 * 8;
            unsigned dst = sb + buf * ATILE + row * ARS + q8 * 16;
            asm volatile("cp.async.cg.shared.global [%0], [%1], 16;"
                         :: "r"(dst), "l"(src) : "memory");
        }
        asm volatile("cp.async.commit_group;" ::: "memory");
    };

    issue_tile(0);
    for (int kt = 0; kt < ntiles; kt++) {
        if (kt + 1 < ntiles) {
            issue_tile(kt + 1);
            asm volatile("cp.async.wait_group 1;" ::: "memory");
        } else {
            asm volatile("cp.async.wait_group 0;" ::: "memory");
        }
        __syncthreads();

        const unsigned stb = sb0 + (kt & 1) * ASTAGE;
        const int kbase = kt * 64;

        // ---- S = Q K^T ----
        float s[8][4] = {};
        #pragma unroll
        for (int kb = 0; kb < 4; kb++) {
            unsigned kfH[4][4], kfL[4][4];
            #pragma unroll
            for (int ng = 0; ng < 4; ng++) {
                unsigned ad = stb + (unsigned)(ng * 16) * ARS + kb * 32 + bOff;
                LDSM4(kfH[ng][0], kfH[ng][1], kfH[ng][2], kfH[ng][3], ad);
                LDSM4(kfL[ng][0], kfL[ng][1], kfL[ng][2], kfL[ng][3], ad + ATILE);
            }
            #pragma unroll
            for (int ng = 0; ng < 4; ng++) {
                BF16MMA(s[ng*2],   qaH[kb], (kfH[ng] + 0));
                BF16MMA(s[ng*2],   qaL[kb], (kfH[ng] + 0));
                BF16MMA(s[ng*2],   qaH[kb], (kfL[ng] + 0));
                BF16MMA(s[ng*2+1], qaH[kb], (kfH[ng] + 2));
                BF16MMA(s[ng*2+1], qaL[kb], (kfH[ng] + 2));
                BF16MMA(s[ng*2+1], qaH[kb], (kfL[ng] + 2));
            }
        }

        // ---- causal mask (diagonal tile) ----
        if (kt == qb) {
            int row0 = qb * 64 + w * 16 + lq;
            #pragma unroll
            for (int ni = 0; ni < 8; ni++) {
                int col = kbase + ni * 8 + 2 * lr;
                if (col     > row0)     s[ni][0] = -1e30f;
                if (col + 1 > row0)     s[ni][1] = -1e30f;
                if (col     > row0 + 8) s[ni][2] = -1e30f;
                if (col + 1 > row0 + 8) s[ni][3] = -1e30f;
            }
        }

        // ---- online softmax ----
        float mt0 = -1e30f, mt1 = -1e30f;
        #pragma unroll
        for (int ni = 0; ni < 8; ni++) {
            mt0 = fmaxf(mt0, fmaxf(s[ni][0], s[ni][1]));
            mt1 = fmaxf(mt1, fmaxf(s[ni][2], s[ni][3]));
        }
        mt0 = fmaxf(mt0, __shfl_xor_sync(0xffffffffu, mt0, 1));
        mt0 = fmaxf(mt0, __shfl_xor_sync(0xffffffffu, mt0, 2));
        mt1 = fmaxf(mt1, __shfl_xor_sync(0xffffffffu, mt1, 1));
        mt1 = fmaxf(mt1, __shfl_xor_sync(0xffffffffu, mt1, 2));
        float mn0 = fmaxf(m0, mt0), mn1 = fmaxf(m1, mt1);
        float c0 = __expf(m0 - mn0), c1 = __expf(m1 - mn1);
        m0 = mn0; m1 = mn1;
        float rs0 = 0.f, rs1 = 0.f;
        #pragma unroll
        for (int ni = 0; ni < 8; ni++) {
            s[ni][0] = __expf(s[ni][0] - mn0);
            s[ni][1] = __expf(s[ni][1] - mn0);
            s[ni][2] = __expf(s[ni][2] - mn1);
            s[ni][3] = __expf(s[ni][3] - mn1);
            rs0 += s[ni][0] + s[ni][1];
            rs1 += s[ni][2] + s[ni][3];
        }
        rs0 += __shfl_xor_sync(0xffffffffu, rs0, 1);
        rs0 += __shfl_xor_sync(0xffffffffu, rs0, 2);
        rs1 += __shfl_xor_sync(0xffffffffu, rs1, 1);
        rs1 += __shfl_xor_sync(0xffffffffu, rs1, 2);
        l0 = l0 * c0 + rs0;
        l1 = l1 * c1 + rs1;
        #pragma unroll
        for (int dn = 0; dn < 8; dn++) {
            acc[dn][0] *= c0; acc[dn][1] *= c0;
            acc[dn][2] *= c1; acc[dn][3] *= c1;
        }

        // ---- O += P V ----
        #pragma unroll
        for (int kb = 0; kb < 4; kb++) {
            unsigned aPH[4], aPL[4];
            split2(s[2*kb][0],   s[2*kb][1],   aPH[0], aPL[0]);
            split2(s[2*kb][2],   s[2*kb][3],   aPH[1], aPL[1]);
            split2(s[2*kb+1][0], s[2*kb+1][1], aPH[2], aPL[2]);
            split2(s[2*kb+1][2], s[2*kb+1][3], aPH[3], aPL[3]);
            #pragma unroll
            for (int dn = 0; dn < 4; dn++) {
                unsigned vfH[4], vfL[4];
                unsigned ad = stb + 2 * ATILE + (unsigned)(kb * 16) * ARS
                            + (unsigned)(dn * 16) * 2 + aOff;
                LDSM4T(vfH[0], vfH[1], vfH[2], vfH[3], ad);
                LDSM4T(vfL[0], vfL[1], vfL[2], vfL[3], ad + ATILE);
                float* acc0 = acc[dn * 2];
                float* acc1 = acc[dn * 2 + 1];
                BF16MMA(acc0, aPH, (vfH + 0));
                BF16MMA(acc0, aPL, (vfH + 0));
                BF16MMA(acc0, aPH, (vfL + 0));
                BF16MMA(acc1, aPH, (vfH + 2));
                BF16MMA(acc1, aPL, (vfH + 2));
                BF16MMA(acc1, aPH, (vfL + 2));
            }
        }
        __syncthreads();
    }

    // ---- epilogue: write split O ----
    float inv0 = 1.f / l0, inv1 = 1.f / l1;
    int row0 = qb * 64 + w * 16 + lq;
    size_t b0 = ((size_t)(b * SS + row0) * HH + hd) * DK;
    size_t b1 = b0 + (size_t)8 * HH * DK;
    #pragma unroll
    for (int dn = 0; dn < 8; dn++) {
        int d = dn * 8 + 2 * lr;
        unsigned h_, l_;
        split2(acc[dn][0] * inv0, acc[dn][1] * inv0, h_, l_);
        *(unsigned*)(OH + b0 + d) = h_;
        *(unsigned*)(OL + b0 + d) = l_;
        split2(acc[dn][2] * inv1, acc[dn][3] * inv1, h_, l_);
        *(unsigned*)(OH + b1 + d) = h_;
        *(unsigned*)(OL + b1 + d) = l_;
    }
}

// ========== pure-bf16 split GEMM, cp.async 3-stage, ldmatrix ===============
#define G_BK 32
#define G_RS 80

template<int BN>
__global__ __launch_bounds__(256)
void gemm_bb_kernel(const __nv_bfloat16* __restrict__ AH_, const __nv_bfloat16* __restrict__ AL_,
                    const __nv_bfloat16* __restrict__ BH_, const __nv_bfloat16* __restrict__ BL_,
                    const float* __restrict__ bias, const float* __restrict__ res,
                    float* __restrict__ C, int Nd, int Kd) {
    constexpr int NG      = BN / 64;
    constexpr unsigned OFF_AL = 128 * G_RS;
    constexpr unsigned OFF_BH = 256 * G_RS;
    constexpr unsigned OFF_BL = (256 + BN) * G_RS;
    constexpr unsigned STAGE  = (256 + 2 * BN) * G_RS;
    constexpr int CH_B    = BN * 4;

    extern __shared__ char smem[];
    const unsigned sbase = smem_u32(smem);
    const int t    = threadIdx.x;
    const int lane = t & 31;
    const int warp = t >> 5;
    const int wm   = warp >> 2;
    const int wn   = warp & 3;
    const int bm   = blockIdx.y * 128;
    const int bn   = blockIdx.x * BN;

    float acc[4][2 * NG][4] = {};
    const int nkt = Kd / G_BK;

    auto issue_stage = [&](int kt) {
        const int k0 = kt * G_BK;
        unsigned sb = sbase + (kt % 3) * STAGE;
        #pragma unroll
        for (int i = 0; i < 4; i++) {
            int c = t + i * 256;
            const __nv_bfloat16* base = (c < 512) ? AH_ : AL_;
            unsigned offt = (c < 512) ? 0u : OFF_AL;
            int cc = c & 511;
            int row = cc >> 2, quad = cc & 3;
            const __nv_bfloat16* src = base + (size_t)(bm + row) * Kd + k0 + quad * 8;
            unsigned dst = sb + offt + row * G_RS + quad * 16;
            asm volatile("cp.async.cg.shared.global [%0], [%1], 16;"
                         :: "r"(dst), "l"(src) : "memory");
        }
        #pragma unroll
        for (int i = 0; i < BN / 32; i++) {
            int c = t + i * 256;
            const __nv_bfloat16* base = (c < CH_B) ? BH_ : BL_;
            unsigned offt = (c < CH_B) ? OFF_BH : OFF_BL;
            int cc = c & (CH_B - 1);
            int row = cc >> 2, quad = cc & 3;
            const __nv_bfloat16* src = base + (size_t)(bn + row) * Kd + k0 + quad * 8;
            unsigned dst = sb + offt + row * G_RS + quad * 16;
            int vsz = (bn + row < Nd) ? 16 : 0;
            asm volatile("cp.async.cg.shared.global [%0], [%1], 16, %2;"
                         :: "r"(dst), "l"(src), "r"(vsz) : "memory");
        }
        asm volatile("cp.async.commit_group;" ::: "memory");
    };

    issue_stage(0);
    issue_stage(1);

    const int m0 = wm * 64;
    const int n0 = wn * (BN / 4);
    const int lq = lane >> 2;
    const int lr = lane & 3;
    const unsigned aRowOff = (unsigned)(lane & 15) * G_RS + (unsigned)(lane >> 4) * 16;
    const unsigned bRowOff = ((unsigned)((lane >> 4) * 8 + (lane & 7))) * G_RS
                           + (unsigned)((lane >> 3) & 1) * 16;

    for (int kt = 0; kt < nkt; kt++) {
        asm volatile("cp.async.wait_group 1;" ::: "memory");
        __syncthreads();
        if (kt + 2 < nkt) issue_stage(kt + 2);
        else asm volatile("cp.async.commit_group;" ::: "memory");

        const unsigned stb = sbase + (kt % 3) * STAGE;
        #pragma unroll
        for (int ks = 0; ks < 2; ks++) {
            unsigned aH[4][4], aL[4][4], bH[NG][4], bL[NG][4];
            const unsigned ksb = ks * 32;
            #pragma unroll
            for (int mi = 0; mi < 4; mi++) {
                unsigned ah = stb + (m0 + mi * 16) * G_RS + ksb + aRowOff;
                unsigned al = ah + OFF_AL;
                LDSM4(aH[mi][0], aH[mi][1], aH[mi][2], aH[mi][3], ah);
                LDSM4(aL[mi][0], aL[mi][1], aL[mi][2], aL[mi][3], al);
            }
            #pragma unroll
            for (int ng = 0; ng < NG; ng++) {
                unsigned bhh = stb + OFF_BH + (n0 + ng * 16) * G_RS + ksb + bRowOff;
                unsigned bll = bhh + (unsigned)(BN * G_RS);
                LDSM4(bH[ng][0], bH[ng][1], bH[ng][2], bH[ng][3], bhh);
                LDSM4(bL[ng][0], bL[ng][1], bL[ng][2], bL[ng][3], bll);
            }
            #pragma unroll
            for (int mi = 0; mi < 4; mi++)
                #pragma unroll
                for (int ng = 0; ng < NG; ng++) {
                    float* acc0 = acc[mi][ng * 2];
                    float* acc1 = acc[mi][ng * 2 + 1];
                    BF16MMA(acc0, aH[mi], (bH[ng] + 0));
                    BF16MMA(acc0, aL[mi], (bH[ng] + 0));
                    BF16MMA(acc0, aH[mi], (bL[ng] + 0));
                    BF16MMA(acc1, aH[mi], (bH[ng] + 2));
                    BF16MMA(acc1, aL[mi], (bH[ng] + 2));
                    BF16MMA(acc1, aH[mi], (bL[ng] + 2));
                }
        }
    }

    #pragma unroll
    for (int mi = 0; mi < 4; mi++) {
        int row = bm + m0 + mi * 16 + lq;
        #pragma unroll
        for (int ni = 0; ni < 2 * NG; ni++) {
            int col = bn + n0 + ni * 8 + lr * 2;
            if (col < Nd) {
                float v0 = acc[mi][ni][0], v1 = acc[mi][ni][1];
                float v2 = acc[mi][ni][2], v3 = acc[mi][ni][3];
                if (bias) {
                    float bx = bias[col], by = bias[col + 1];
                    v0 += bx; v1 += by; v2 += bx; v3 += by;
                }
                size_t o0 = (size_t)row * Nd + col;
                size_t o1 = (size_t)(row + 8) * Nd + col;
                if (res) {
                    v0 += res[o0]; v1 += res[o0 + 1];
                    v2 += res[o1]; v3 += res[o1 + 1];
                }
                C[o0] = v0; C[o0 + 1] = v1;
                C[o1] = v2; C[o1 + 1] = v3;
            }
        }
    }
}

#define SM128 ((256 + 2 * 128) * G_RS * 3)    // 122880
#define SM256 ((256 + 2 * 256) * G_RS * 3)    // 184320

// ---------------- silu(f1)*f2 -> split ----------------
__global__ void silumul_split_kernel(const float* __restrict__ f1,
                                     const float* __restrict__ f2,
                                     __nv_bfloat16* __restrict__ H,
                                     __nv_bfloat16* __restrict__ L) {
    size_t i = (size_t)blockIdx.x * 256 + threadIdx.x;
    float2 a = ((const float2*)f1)[i];
    float2 b = ((const float2*)f2)[i];
    float g0 = a.x / (1.0f + __expf(-a.x)) * b.x;
    float g1 = a.y / (1.0f + __expf(-a.y)) * b.y;
    unsigned h_, l_;
    split2(g0, g1, h_, l_);
    ((unsigned*)H)[i] = h_;
    ((unsigned*)L)[i] = l_;
}

// ---------------- host driver ----------------
extern "C" void kernel_launch(void* const* d_in, const int* in_sizes, int n_in,
                              void* d_out, int out_size) {
    const int*   tokens = (const int*)  d_in[0];
    const float* emb    = (const float*)d_in[1];
    const float* wq = (const float*)d_in[2];
    const float* bq = (const float*)d_in[3];
    const float* wk = (const float*)d_in[4];
    const float* bk = (const float*)d_in[5];
    const float* wv = (const float*)d_in[6];
    const float* bv = (const float*)d_in[7];
    const float* wo = (const float*)d_in[8];
    const float* bo = (const float*)d_in[9];
    const float* w1 = (const float*)d_in[10];
    const float* b1 = (const float*)d_in[11];
    const float* w2 = (const float*)d_in[12];
    const float* b2 = (const float*)d_in[13];
    const float* w3 = (const float*)d_in[14];
    const float* b3 = (const float*)d_in[15];
    const float* g1 = (const float*)d_in[16];
    const float* g2 = (const float*)d_in[17];
    const float* gpost = (const float*)d_in[18];
    const float* fcos  = (const float*)d_in[19];
    const float* fsin  = (const float*)d_in[20];
    float* out = (float*)d_out;

    float *x, *q, *kv, *f1, *f2, *bkv;
    __nv_bfloat16 *hH, *hL, *oH, *oL, *kvH, *kvL, *f1H, *f1L;
    __nv_bfloat16 *wqH, *wqL, *wkvH, *wkvL, *woH, *woL;
    __nv_bfloat16 *w1H, *w1L, *w2H, *w2L, *w3H, *w3L, *ebH, *ebL;
    cudaGetSymbolAddress((void**)&x,   g_x);
    cudaGetSymbolAddress((void**)&q,   g_q);
    cudaGetSymbolAddress((void**)&kv,  g_kv);
    cudaGetSymbolAddress((void**)&f1,  g_f1);
    cudaGetSymbolAddress((void**)&f2,  g_f2);
    cudaGetSymbolAddress((void**)&bkv, g_bkv);
    cudaGetSymbolAddress((void**)&hH,  g_hH);   cudaGetSymbolAddress((void**)&hL,  g_hL);
    cudaGetSymbolAddress((void**)&oH,  g_oH);   cudaGetSymbolAddress((void**)&oL,  g_oL);
    cudaGetSymbolAddress((void**)&kvH, g_kvH);  cudaGetSymbolAddress((void**)&kvL, g_kvL);
    cudaGetSymbolAddress((void**)&f1H, g_f1H);  cudaGetSymbolAddress((void**)&f1L, g_f1L);
    cudaGetSymbolAddress((void**)&wqH, g_wqH);  cudaGetSymbolAddress((void**)&wqL, g_wqL);
    cudaGetSymbolAddress((void**)&wkvH, g_wkvH); cudaGetSymbolAddress((void**)&wkvL, g_wkvL);
    cudaGetSymbolAddress((void**)&woH, g_woH);  cudaGetSymbolAddress((void**)&woL, g_woL);
    cudaGetSymbolAddress((void**)&w1H, g_w1H);  cudaGetSymbolAddress((void**)&w1L, g_w1L);
    cudaGetSymbolAddress((void**)&w2H, g_w2H);  cudaGetSymbolAddress((void**)&w2L, g_w2L);
    cudaGetSymbolAddress((void**)&w3H, g_w3H);  cudaGetSymbolAddress((void**)&w3L, g_w3L);
    cudaGetSymbolAddress((void**)&ebH, g_ebH);  cudaGetSymbolAddress((void**)&ebL, g_ebL);

    cudaFuncSetAttribute(gemm_bb_kernel<128>,
                         cudaFuncAttributeMaxDynamicSharedMemorySize, SM128);
    cudaFuncSetAttribute(gemm_bb_kernel<256>,
                         cudaFuncAttributeMaxDynamicSharedMemorySize, SM256);
    cudaFuncSetAttribute(attn_tc_kernel,
                         cudaFuncAttributeMaxDynamicSharedMemorySize, ASMEM);

    // ---- conversions (inside graph) ----
    esplit_kernel<<<(VV * DD) / (256 * 4), 256>>>(emb, ebH, ebL);
    bkv_kernel<<<NL, 512>>>(bk, bv, bkv);
    dim3 tb(32, 8);
    for (int l = 0; l < NL; l++) {
        tsplit_kernel<<<dim3(DD / 32, DD / 32), tb>>>(
            wq + (size_t)l * DD * DD, wqH + (size_t)l * DD * DD, wqL + (size_t)l * DD * DD, DD, DD);
        tsplit_kernel<<<dim3(KVN / 32, DD / 32), tb>>>(
            wk + (size_t)l * DD * KVN,
            wkvH + (size_t)l * 1024 * DD, wkvL + (size_t)l * 1024 * DD, DD, KVN);
        tsplit_kernel<<<dim3(KVN / 32, DD / 32), tb>>>(
            wv + (size_t)l * DD * KVN,
            wkvH + (size_t)l * 1024 * DD + (size_t)512 * DD,
            wkvL + (size_t)l * 1024 * DD + (size_t)512 * DD, DD, KVN);
        tsplit_kernel<<<dim3(DD / 32, DD / 32), tb>>>(
            wo + (size_t)l * DD * DD, woH + (size_t)l * DD * DD, woL + (size_t)l * DD * DD, DD, DD);
        tsplit_kernel<<<dim3(FD / 32, DD / 32), tb>>>(
            w1 + (size_t)l * DD * FD, w1H + (size_t)l * DD * FD, w1L + (size_t)l * DD * FD, DD, FD);
        tsplit_kernel<<<dim3(FD / 32, DD / 32), tb>>>(
            w2 + (size_t)l * DD * FD, w2H + (size_t)l * DD * FD, w2L + (size_t)l * DD * FD, DD, FD);
        tsplit_kernel<<<dim3(DD / 32, FD / 32), tb>>>(
            w3 + (size_t)l * FD * DD, w3H + (size_t)l * FD * DD, w3L + (size_t)l * FD * DD, FD, DD);
    }

    embed_kernel<<<MM, 256>>>(tokens, emb, x);

    const int GY = MM / 128;    // 32
    for (int l = 0; l < NL; l++) {
        rmsnorm_split_kernel<<<MM, 256>>>(x, g1 + (size_t)l * DD, hH, hL);

        gemm_bb_kernel<256><<<dim3(DD / 256, GY), 256, SM256>>>(
            hH, hL, wqH + (size_t)l * DD * DD, wqL + (size_t)l * DD * DD,
            bq + (size_t)l * DD, nullptr, q, DD, DD);
        gemm_bb_kernel<256><<<dim3(1024 / 256, GY), 256, SM256>>>(
            hH, hL, wkvH + (size_t)l * 1024 * DD, wkvL + (size_t)l * 1024 * DD,
            bkv + (size_t)l * 1024, nullptr, kv, 1024, DD);

        int tq = MM * HH * 32;
        rope_kernel<<<(tq + 255) / 256, 256>>>(q, fcos, fsin, HH, tq);
        kvsplit_rope_kernel<<<MM, 256>>>(kv, fcos, fsin, kvH, kvL);

        attn_tc_kernel<<<dim3(SS / 64, HH, BB), 128, ASMEM>>>(q, kvH, kvL, oH, oL);

        gemm_bb_kernel<256><<<dim3(DD / 256, GY), 256, SM256>>>(
            oH, oL, woH + (size_t)l * DD * DD, woL + (size_t)l * DD * DD,
            bo + (size_t)l * DD, x, x, DD, DD);

        rmsnorm_split_kernel<<<MM, 256>>>(x, g2 + (size_t)l * DD, hH, hL);

        int gnx = (FD + 255) / 256;   // 11
        gemm_bb_kernel<256><<<dim3(gnx, GY), 256, SM256>>>(
            hH, hL, w1H + (size_t)l * DD * FD, w1L + (size_t)l * DD * FD,
            b1 + (size_t)l * FD, nullptr, f1, FD, DD);
        gemm_bb_kernel<256><<<dim3(gnx, GY), 256, SM256>>>(
            hH, hL, w2H + (size_t)l * DD * FD, w2L + (size_t)l * DD * FD,
            b2 + (size_t)l * FD, nullptr, f2, FD, DD);

        silumul_split_kernel<<<(MM * (FD / 2)) / 256, 256>>>(f1, f2, f1H, f1L);

        gemm_bb_kernel<256><<<dim3(DD / 256, GY), 256, SM256>>>(
            f1H, f1L, w3H + (size_t)l * FD * DD, w3L + (size_t)l * FD * DD,
            b3 + (size_t)l * DD, x, x, DD, FD);
    }

    rmsnorm_split_kernel<<<MM, 256>>>(x, gpost, hH, hL);
    gemm_bb_kernel<256><<<dim3(VV / 256, GY), 256, SM256>>>(
        hH, hL, ebH, ebL, nullptr, nullptr, out, VV, DD);
}